// round 1
// baseline (speedup 1.0000x reference)
#include <cuda_runtime.h>
#include <math.h>

#define BATCH 2
#define N1 4096
#define N2 4096
#define DD 64
#define KN 16
#define KCC 8
#define CP 80      // padded feature channels (67 / 70 used)
#define CO 128

// ---------------- scratch (static device memory; no runtime alloc) ----------------
__device__ float g_dist[(size_t)BATCH * N1 * N2];        // 134 MB
__device__ float g_F1[BATCH * CP * N1];
__device__ float g_F2[BATCH * CP * N2];
__device__ float g_CB[BATCH * CP * N1];
__device__ float g_nA[BATCH * N1];
__device__ float g_nB[BATCH * N2];
__device__ float g_nC[BATCH * N1];
__device__ int   g_idx1[BATCH * N1 * KN];
__device__ int   g_idx2[BATCH * N1 * KN];
__device__ float g_vw[BATCH * N1 * 3];
__device__ float g_wf[BATCH * N1];
__device__ float g_wr[BATCH * N1];
__device__ float g_p1T[BATCH * N1 * DD];
__device__ float g_p2T[BATCH * N2 * DD];
__device__ float g_x1T[BATCH * N1 * 3];
__device__ float g_x2T[BATCH * N2 * 3];
__device__ float g_p2p[(size_t)BATCH * N1 * CO];

__device__ __forceinline__ float leakyf(float x) { return x >= 0.f ? x : 0.1f * x; }

// ---------------- rigid 3x3 least squares + mask ----------------
__global__ void k_rigid(const float* __restrict__ xyz1, const float* __restrict__ vel1,
                        const float* __restrict__ fcc, const float* __restrict__ fcv,
                        float* __restrict__ out_vw)
{
    int t = blockIdx.x * blockDim.x + threadIdx.x;
    if (t >= BATCH * N1) return;
    int b = t / N1, n = t % N1;
    const float* cc = fcc + (size_t)t * KCC * 3;
    const float* cv = fcv + (size_t)t * KCC;
    double A00 = 1e-6, A01 = 0, A02 = 0, A11 = 1e-6, A12 = 0, A22 = 1e-6;
    double r0 = 0, r1 = 0, r2 = 0;
    for (int k = 0; k < KCC; k++) {
        double x = cc[k * 3 + 0], y = cc[k * 3 + 1], z = cc[k * 3 + 2];
        double inv = 1.0 / sqrt(x * x + y * y + z * z);
        x *= inv; y *= inv; z *= inv;
        A00 += x * x; A01 += x * y; A02 += x * z;
        A11 += y * y; A12 += y * z; A22 += z * z;
        double v = (double)cv[k];
        r0 += x * v; r1 += y * v; r2 += z * v;
    }
    double c00 = A11 * A22 - A12 * A12;
    double c01 = A01 * A22 - A12 * A02;
    double c02 = A01 * A12 - A11 * A02;
    double det = A00 * c00 - A01 * c01 + A02 * c02;
    double id = 1.0 / det;
    double v0 = (r0 * c00 - A01 * (r1 * A22 - A12 * r2) + A02 * (r1 * A12 - A11 * r2)) * id;
    double v1 = (A00 * (r1 * A22 - A12 * r2) - r0 * c01 + A02 * (A01 * r2 - r1 * A02)) * id;
    double v2 = (A00 * (A11 * r2 - r1 * A12) - A01 * (A01 * r2 - r1 * A02) + r0 * c02) * id;

    float fx = xyz1[(b * 3 + 0) * N1 + n];
    float fy = xyz1[(b * 3 + 1) * N1 + n];
    float fz = xyz1[(b * 3 + 2) * N1 + n];
    double inl = 1.0 / sqrt((double)fx * fx + (double)fy * fy + (double)fz * fz);
    double err = fabs((v0 * fx + v1 * fy + v2 * fz) * inl - (double)vel1[t]);
    bool m = (err <= 5.0);
    g_wf[t] = m ? 0.1f : 0.9f;
    g_wr[t] = m ? 0.9f : 0.1f;
    g_vw[t * 3 + 0] = (float)v0;
    g_vw[t * 3 + 1] = (float)v1;
    g_vw[t * 3 + 2] = (float)v2;
    if (out_vw) {
        out_vw[t * 3 + 0] = (float)v0;
        out_vw[t * 3 + 1] = (float)v1;
        out_vw[t * 3 + 2] = (float)v2;
    }
}

// ---------------- build weighted feature matrices F1,F2 (channel-major, zero pad) ----------------
__global__ void k_feat(const float* __restrict__ xyz1, const float* __restrict__ xyz2,
                       const float* __restrict__ pts1, const float* __restrict__ pts2,
                       const float* __restrict__ wxyz_p, const float* __restrict__ wpts_p)
{
    float wx = *wxyz_p, wp = *wpts_p;
    const int total = BATCH * CP * N1;
    for (int e = blockIdx.x * blockDim.x + threadIdx.x; e < 2 * total;
         e += gridDim.x * blockDim.x) {
        int which = e / total;
        int r = e % total;
        int b = r / (CP * N1);
        int c = (r / N1) % CP;
        int n = r % N1;
        const float* xyz = which ? xyz2 : xyz1;
        const float* pts = which ? pts2 : pts1;
        float* F = which ? g_F2 : g_F1;
        float v = 0.f;
        if (c < 3) v = wx * xyz[(b * 3 + c) * N1 + n];
        else if (c < 67) v = wp * pts[(b * DD + (c - 3)) * N1 + n];
        F[r] = v;
    }
}

// ---------------- transposes to point-major ----------------
__global__ void k_trans(const float* __restrict__ pts1, const float* __restrict__ pts2,
                        const float* __restrict__ xyz1, const float* __restrict__ xyz2)
{
    const int tp = BATCH * DD * N1;
    const int tx3 = BATCH * 3 * N1;
    const int total = 2 * tp + 2 * tx3;
    for (int e = blockIdx.x * blockDim.x + threadIdx.x; e < total;
         e += gridDim.x * blockDim.x) {
        if (e < tp) {
            int b = e / (DD * N1), c = (e / N1) % DD, n = e % N1;
            g_p1T[((size_t)b * N1 + n) * DD + c] = pts1[e];
        } else if (e < 2 * tp) {
            int r = e - tp;
            int b = r / (DD * N1), c = (r / N1) % DD, n = r % N1;
            g_p2T[((size_t)b * N2 + n) * DD + c] = pts2[r];
        } else if (e < 2 * tp + tx3) {
            int r = e - 2 * tp;
            int b = r / (3 * N1), c = (r / N1) % 3, n = r % N1;
            g_x1T[(b * N1 + n) * 3 + c] = xyz1[r];
        } else {
            int r = e - 2 * tp - tx3;
            int b = r / (3 * N1), c = (r / N1) % 3, n = r % N1;
            g_x2T[(b * N2 + n) * 3 + c] = xyz2[r];
        }
    }
}

// ---------------- squared norms ----------------
__global__ void k_norm(int sel)
{
    int t = blockIdx.x * blockDim.x + threadIdx.x;
    if (t >= BATCH * 4096) return;
    int b = t / 4096, n = t % 4096;
    const float* F = (sel == 0) ? g_F1 : (sel == 1) ? g_F2 : g_CB;
    float* o = (sel == 0) ? g_nA : (sel == 1) ? g_nB : g_nC;
    float s = 0.f;
    #pragma unroll 8
    for (int c = 0; c < CP; c++) {
        float v = F[(b * CP + c) * 4096 + n];
        s += v * v;
    }
    o[t] = s;
}

// ---------------- comb features for second KNN ----------------
__global__ void k_comb()
{
    const int total = BATCH * CP * N1;
    for (int e = blockIdx.x * blockDim.x + threadIdx.x; e < total;
         e += gridDim.x * blockDim.x) {
        int b = e / (CP * N1);
        int c = (e / N1) % CP;
        int n = e % N1;
        float v = 0.f;
        if (c < 67) v = g_wf[b * N1 + n] * g_F1[e];
        else if (c < 70) v = g_wr[b * N1 + n] * g_vw[(b * N1 + n) * 3 + (c - 67)];
        g_CB[e] = v;
    }
}

// ---------------- distance matrix GEMM: d = |a|^2 - 2 a.b + |b|^2 (clamped) ----------------
__global__ void __launch_bounds__(256) k_dist(int sel)
{
    __shared__ float As[16][132];
    __shared__ float Bs[16][132];
    const float* FA = sel ? g_CB : g_F1;
    const float* FB = sel ? g_CB : g_F2;
    const float* nAv = sel ? g_nC : g_nA;
    const float* nBv = sel ? g_nC : g_nB;

    int b = blockIdx.z;
    int i0 = blockIdx.y * 128, j0 = blockIdx.x * 128;
    const float* Ab = FA + (size_t)b * CP * N1;
    const float* Bb = FB + (size_t)b * CP * N2;
    int tid = threadIdx.x;
    int tx = tid & 15, ty = tid >> 4;

    float acc[8][8];
    #pragma unroll
    for (int r = 0; r < 8; r++)
        #pragma unroll
        for (int s = 0; s < 8; s++) acc[r][s] = 0.f;

    for (int kc = 0; kc < CP; kc += 16) {
        #pragma unroll
        for (int l = 0; l < 8; l++) {
            int e = tid + l * 256;
            int r = e >> 7, c = e & 127;
            As[r][c] = Ab[(kc + r) * N1 + i0 + c];
            Bs[r][c] = Bb[(kc + r) * N2 + j0 + c];
        }
        __syncthreads();
        #pragma unroll
        for (int kk = 0; kk < 16; kk++) {
            float ar[8], br[8];
            #pragma unroll
            for (int u = 0; u < 4; u++) {
                ar[u] = As[kk][ty * 4 + u];
                ar[4 + u] = As[kk][64 + ty * 4 + u];
                br[u] = Bs[kk][tx * 4 + u];
                br[4 + u] = Bs[kk][64 + tx * 4 + u];
            }
            #pragma unroll
            for (int r = 0; r < 8; r++)
                #pragma unroll
                for (int s = 0; s < 8; s++) acc[r][s] += ar[r] * br[s];
        }
        __syncthreads();
    }
    float* drow = g_dist + (size_t)b * N1 * N2;
    #pragma unroll
    for (int r = 0; r < 8; r++) {
        int i = i0 + ((r < 4) ? (ty * 4 + r) : (64 + ty * 4 + (r - 4)));
        float ni = nAv[b * N1 + i];
        #pragma unroll
        for (int s = 0; s < 8; s++) {
            int j = j0 + ((s < 4) ? (tx * 4 + s) : (64 + tx * 4 + (s - 4)));
            float d = ni - 2.f * acc[r][s] + nBv[b * N2 + j];
            drow[(size_t)i * N2 + j] = fmaxf(d, 0.f);
        }
    }
}

// ---------------- exact top-K selection (jax tie-break: smaller dist, then smaller idx) ----------------
__global__ void __launch_bounds__(128) k_topk(int sel)
{
    __shared__ unsigned long long keys[N2];   // 32 KB
    __shared__ unsigned long long red[4];
    int q = blockIdx.x;
    const float* row = g_dist + (size_t)q * N2;
    int* idxo = sel ? g_idx2 : g_idx1;
    int tid = threadIdx.x;
    for (int j = tid; j < N2; j += 128) {
        unsigned int fb = __float_as_uint(row[j]);  // non-negative -> order-preserving bits
        keys[j] = ((unsigned long long)fb << 32) | (unsigned)j;
    }
    __syncthreads();
    for (int k = 0; k < KN; k++) {
        unsigned long long m = 0xFFFFFFFFFFFFFFFFULL;
        for (int j = tid; j < N2; j += 128) {
            unsigned long long v = keys[j];
            m = (v < m) ? v : m;
        }
        #pragma unroll
        for (int o = 16; o; o >>= 1) {
            unsigned long long v = __shfl_xor_sync(0xffffffffu, m, o);
            m = (v < m) ? v : m;
        }
        if ((tid & 31) == 0) red[tid >> 5] = m;
        __syncthreads();
        if (tid == 0) {
            m = red[0];
            if (red[1] < m) m = red[1];
            if (red[2] < m) m = red[2];
            if (red[3] < m) m = red[3];
            int j = (int)(unsigned)(m & 0xffffffffULL);
            idxo[q * KN + k] = j;
            keys[j] = 0xFFFFFFFFFFFFFFFFULL;
        }
        __syncthreads();
    }
}

// ---------------- fused neighbor-MLP + weightnet1 + K-reduce -> p2p ----------------
#define TNP 4
#define SW 133
#define SM_W (128 * SW)
#define SM_A (TNP * 131 * 16)
#define SM_B (TNP * 128 * 16)
#define SM_H (TNP * 16 * 8)
#define SM_P 256
#define MLP_SMEM (((size_t)SM_W + SM_A + SM_B + SM_H + SM_P) * 4 + TNP * KN * 4)

__global__ void __launch_bounds__(256) k_mlp(
    const float* __restrict__ w0g, const float* __restrict__ b0g,
    const float* __restrict__ w1g, const float* __restrict__ b1g,
    const float* __restrict__ w2g, const float* __restrict__ b2g,
    const float* __restrict__ n1w0, const float* __restrict__ n1b0,
    const float* __restrict__ n1w1, const float* __restrict__ n1b1,
    const float* __restrict__ n1w2, const float* __restrict__ n1b2)
{
    extern __shared__ float sm[];
    float* Wsm = sm;
    float* Abuf = Wsm + SM_W;
    float* Bbuf = Abuf + SM_A;
    float* h2s = Bbuf + SM_B;
    float* psum = h2s + SM_H;
    int* idxs = (int*)(psum + SM_P);

    int tid = threadIdx.x;
    int base = blockIdx.x * TNP;  // point index over BATCH*N1

    if (tid < TNP * KN) idxs[tid] = g_idx1[base * KN + tid];
    __syncthreads();

    // build input tile: [tn][i(131)][k(16)]
    for (int e = tid; e < TNP * 16 * 131; e += 256) {
        int tn = e / (16 * 131);
        int rem = e % (16 * 131);
        int k = rem / 131;
        int i = rem % 131;
        int pt = base + tn;
        int b = pt / N1;
        int j = idxs[tn * KN + k];
        float v;
        if (i < 64) v = g_p1T[(size_t)pt * DD + i];
        else if (i < 128) v = g_p2T[((size_t)b * N2 + j) * DD + (i - 64)];
        else v = g_x2T[(b * N2 + j) * 3 + (i - 128)] - g_x1T[pt * 3 + (i - 128)];
        Abuf[(tn * 131 + i) * 16 + k] = v;
    }
    __syncthreads();

    // weight-net 1 (3->8->8), per (tn,k)
    if (tid < TNP * KN) {
        int tn = tid / KN, k = tid % KN;
        float dx0 = Abuf[(tn * 131 + 128) * 16 + k];
        float dx1 = Abuf[(tn * 131 + 129) * 16 + k];
        float dx2 = Abuf[(tn * 131 + 130) * 16 + k];
        float h[8];
        #pragma unroll
        for (int j = 0; j < 8; j++) {
            float s = n1w0[j * 3 + 0] * dx0 + n1w0[j * 3 + 1] * dx1 + n1w0[j * 3 + 2] * dx2 + n1b0[j];
            h[j] = fmaxf(s, 0.f);
        }
        #pragma unroll
        for (int j = 0; j < 8; j++) {
            float s = n1b1[j];
            #pragma unroll
            for (int m = 0; m < 8; m++) s += n1w1[j * 8 + m] * h[m];
            h2s[(tn * KN + k) * 8 + j] = fmaxf(s, 0.f);
        }
    }

    // stage W0
    for (int e = tid; e < 128 * 131; e += 256) {
        int c = e / 131, i = e % 131;
        Wsm[c * SW + i] = w0g[e];
    }
    __syncthreads();

    int c = tid & 127, kh = tid >> 7;
    float w2r[8];
    #pragma unroll
    for (int j = 0; j < 8; j++) w2r[j] = n1w2[c * 8 + j];
    float b2c = n1b2[c];
    float bias0 = b0g[c], bias1 = b1g[c], bias2 = b2g[c];

    // layer 1: 131 -> 128, leaky
    for (int tn = 0; tn < TNP; tn++) {
        float a[8];
        #pragma unroll
        for (int u = 0; u < 8; u++) a[u] = bias0;
        const float* Ain = Abuf + tn * 131 * 16 + kh * 8;
        #pragma unroll 4
        for (int i = 0; i < 131; i++) {
            float w = Wsm[c * SW + i];
            float4 v0 = *(const float4*)(Ain + i * 16);
            float4 v1 = *(const float4*)(Ain + i * 16 + 4);
            a[0] += w * v0.x; a[1] += w * v0.y; a[2] += w * v0.z; a[3] += w * v0.w;
            a[4] += w * v1.x; a[5] += w * v1.y; a[6] += w * v1.z; a[7] += w * v1.w;
        }
        float* Bo = Bbuf + (tn * 128 + c) * 16 + kh * 8;
        #pragma unroll
        for (int u = 0; u < 8; u++) Bo[u] = leakyf(a[u]);
    }
    __syncthreads();

    // stage W1
    for (int e = tid; e < 128 * 128; e += 256) {
        int cc = e >> 7, i = e & 127;
        Wsm[cc * SW + i] = w1g[e];
    }
    __syncthreads();

    // layer 2: 128 -> 128
    for (int tn = 0; tn < TNP; tn++) {
        float a[8];
        #pragma unroll
        for (int u = 0; u < 8; u++) a[u] = bias1;
        const float* Bin = Bbuf + tn * 128 * 16 + kh * 8;
        #pragma unroll 4
        for (int i = 0; i < 128; i++) {
            float w = Wsm[c * SW + i];
            float4 v0 = *(const float4*)(Bin + i * 16);
            float4 v1 = *(const float4*)(Bin + i * 16 + 4);
            a[0] += w * v0.x; a[1] += w * v0.y; a[2] += w * v0.z; a[3] += w * v0.w;
            a[4] += w * v1.x; a[5] += w * v1.y; a[6] += w * v1.z; a[7] += w * v1.w;
        }
        float* Ao = Abuf + (tn * 131 + c) * 16 + kh * 8;
        #pragma unroll
        for (int u = 0; u < 8; u++) Ao[u] = leakyf(a[u]);
    }
    __syncthreads();

    // stage W2
    for (int e = tid; e < 128 * 128; e += 256) {
        int cc = e >> 7, i = e & 127;
        Wsm[cc * SW + i] = w2g[e];
    }
    __syncthreads();

    // layer 3 + weightnet multiply + K reduction
    for (int tn = 0; tn < TNP; tn++) {
        float a[8];
        #pragma unroll
        for (int u = 0; u < 8; u++) a[u] = bias2;
        const float* Ain = Abuf + tn * 131 * 16 + kh * 8;
        #pragma unroll 4
        for (int i = 0; i < 128; i++) {
            float w = Wsm[c * SW + i];
            float4 v0 = *(const float4*)(Ain + i * 16);
            float4 v1 = *(const float4*)(Ain + i * 16 + 4);
            a[0] += w * v0.x; a[1] += w * v0.y; a[2] += w * v0.z; a[3] += w * v0.w;
            a[4] += w * v1.x; a[5] += w * v1.y; a[6] += w * v1.z; a[7] += w * v1.w;
        }
        float partial = 0.f;
        #pragma unroll
        for (int kk = 0; kk < 8; kk++) {
            float y = leakyf(a[kk]);
            int k = kh * 8 + kk;
            const float* hh = h2s + (tn * KN + k) * 8;
            float s = b2c;
            #pragma unroll
            for (int j = 0; j < 8; j++) s += w2r[j] * hh[j];
            s = fmaxf(s, 0.f);
            partial += s * y;
        }
        psum[tid] = partial;
        __syncthreads();
        if (kh == 0) {
            int pt = base + tn;
            g_p2p[(size_t)pt * CO + c] = psum[c] + psum[128 + c];
        }
        __syncthreads();
    }
}

// ---------------- patch aggregation: weightnet2 + gather p2p + K-reduce ----------------
__global__ void __launch_bounds__(128) k_patch(
    const float* __restrict__ n2w0, const float* __restrict__ n2b0,
    const float* __restrict__ n2w1, const float* __restrict__ n2b1,
    const float* __restrict__ n2w2, const float* __restrict__ n2b2,
    float* __restrict__ out)
{
    __shared__ float h2s[16][8];
    __shared__ int js[16];
    int q = blockIdx.x;
    int b = q / N1, n = q % N1;
    int tid = threadIdx.x;
    if (tid < 16) {
        int j = g_idx2[q * KN + tid];
        js[tid] = j;
        float dx0 = g_x1T[(b * N1 + j) * 3 + 0] - g_x1T[q * 3 + 0];
        float dx1 = g_x1T[(b * N1 + j) * 3 + 1] - g_x1T[q * 3 + 1];
        float dx2 = g_x1T[(b * N1 + j) * 3 + 2] - g_x1T[q * 3 + 2];
        float h[8];
        #pragma unroll
        for (int jj = 0; jj < 8; jj++) {
            float s = n2w0[jj * 3 + 0] * dx0 + n2w0[jj * 3 + 1] * dx1 + n2w0[jj * 3 + 2] * dx2 + n2b0[jj];
            h[jj] = fmaxf(s, 0.f);
        }
        #pragma unroll
        for (int jj = 0; jj < 8; jj++) {
            float s = n2b1[jj];
            #pragma unroll
            for (int m = 0; m < 8; m++) s += n2w1[jj * 8 + m] * h[m];
            h2s[tid][jj] = fmaxf(s, 0.f);
        }
    }
    __syncthreads();
    int c = tid;
    float w2r[8];
    #pragma unroll
    for (int j = 0; j < 8; j++) w2r[j] = n2w2[c * 8 + j];
    float bc = n2b2[c];
    float acc = 0.f;
    #pragma unroll
    for (int k = 0; k < KN; k++) {
        float s = bc;
        #pragma unroll
        for (int j = 0; j < 8; j++) s += w2r[j] * h2s[k][j];
        s = fmaxf(s, 0.f);
        acc += s * g_p2p[((size_t)b * N1 + js[k]) * CO + c];
    }
    out[(size_t)b * CO * N1 + (size_t)c * N1 + n] = acc;
}

// ---------------- launch ----------------
extern "C" void kernel_launch(void* const* d_in, const int* in_sizes, int n_in,
                              void* d_out, int out_size)
{
    // Input layout: masks may or may not be present in metadata; detect via count.
    int s = (n_in >= 31) ? 0 : -2;
    const float* xyz1 = (const float*)d_in[0];
    const float* xyz2 = (const float*)d_in[1];
    const float* pts1 = (const float*)d_in[2];
    const float* pts2 = (const float*)d_in[3];
    const float* vel1 = (const float*)d_in[4];
    const float* fcc  = (const float*)d_in[8 + s];
    const float* fcv  = (const float*)d_in[9 + s];
    const float* wxyz = (const float*)d_in[10 + s];
    const float* wpts = (const float*)d_in[12 + s];
    const float* mw0 = (const float*)d_in[13 + s];
    const float* mb0 = (const float*)d_in[14 + s];
    const float* mw1 = (const float*)d_in[15 + s];
    const float* mb1 = (const float*)d_in[16 + s];
    const float* mw2 = (const float*)d_in[17 + s];
    const float* mb2 = (const float*)d_in[18 + s];
    const float* n1w0 = (const float*)d_in[19 + s];
    const float* n1b0 = (const float*)d_in[20 + s];
    const float* n2w0 = (const float*)d_in[21 + s];
    const float* n2b0 = (const float*)d_in[22 + s];
    const float* n1w1 = (const float*)d_in[23 + s];
    const float* n1b1 = (const float*)d_in[24 + s];
    const float* n2w1 = (const float*)d_in[25 + s];
    const float* n2b1 = (const float*)d_in[26 + s];
    const float* n1w2 = (const float*)d_in[27 + s];
    const float* n1b2 = (const float*)d_in[28 + s];
    const float* n2w2 = (const float*)d_in[29 + s];
    const float* n2b2 = (const float*)d_in[30 + s];

    float* out = (float*)d_out;
    const int patch_elems = BATCH * CO * N1;
    const int vw_elems = BATCH * N1 * 3;
    float* out_vw = (out_size >= patch_elems + vw_elems) ? (out + patch_elems) : nullptr;

    cudaFuncSetAttribute(k_mlp, cudaFuncAttributeMaxDynamicSharedMemorySize, (int)MLP_SMEM);

    k_rigid<<<(BATCH * N1 + 127) / 128, 128>>>(xyz1, vel1, fcc, fcv, out_vw);
    k_feat<<<(2 * BATCH * CP * N1 + 255) / 256, 256>>>(xyz1, xyz2, pts1, pts2, wxyz, wpts);
    k_trans<<<(2 * BATCH * DD * N1 + 2 * BATCH * 3 * N1 + 255) / 256, 256>>>(pts1, pts2, xyz1, xyz2);
    k_norm<<<(BATCH * 4096 + 127) / 128, 128>>>(0);
    k_norm<<<(BATCH * 4096 + 127) / 128, 128>>>(1);
    k_comb<<<(BATCH * CP * N1 + 255) / 256, 256>>>();
    k_norm<<<(BATCH * 4096 + 127) / 128, 128>>>(2);

    dim3 gg(N2 / 128, N1 / 128, BATCH);
    k_dist<<<gg, 256>>>(0);
    k_topk<<<BATCH * N1, 128>>>(0);

    k_mlp<<<(BATCH * N1) / TNP, 256, MLP_SMEM>>>(mw0, mb0, mw1, mb1, mw2, mb2,
                                                 n1w0, n1b0, n1w1, n1b1, n1w2, n1b2);

    k_dist<<<gg, 256>>>(1);
    k_topk<<<BATCH * N1, 128>>>(1);

    k_patch<<<BATCH * N1, 128>>>(n2w0, n2b0, n2w1, n2b1, n2w2, n2b2, out);
}

// round 3
// speedup vs baseline: 1.3170x; 1.3170x over previous
#include <cuda_runtime.h>
#include <math.h>

#define BATCH 2
#define N1 4096
#define N2 4096
#define DD 64
#define KN 16
#define KCC 8
#define CP 80      // padded feature channels (67 / 70 used)
#define CO 128

// ---------------- scratch (static device memory; no runtime alloc) ----------------
__device__ float g_dist[(size_t)BATCH * N1 * N2];        // 134 MB
__device__ float g_F1[BATCH * CP * N1];
__device__ float g_F2[BATCH * CP * N2];
__device__ float g_CB[BATCH * CP * N1];
__device__ float g_nA[BATCH * N1];
__device__ float g_nB[BATCH * N2];
__device__ float g_nC[BATCH * N1];
__device__ int   g_idx1[BATCH * N1 * KN];
__device__ int   g_idx2[BATCH * N1 * KN];
__device__ float g_vw[BATCH * N1 * 3];
__device__ float g_wf[BATCH * N1];
__device__ float g_wr[BATCH * N1];
__device__ float g_p1T[BATCH * N1 * DD];
__device__ float g_p2T[BATCH * N2 * DD];
__device__ float g_x1T[BATCH * N1 * 3];
__device__ float g_x2T[BATCH * N2 * 3];
__device__ float g_p2p[(size_t)BATCH * N1 * CO];

__device__ __forceinline__ float leakyf(float x) { return x >= 0.f ? x : 0.1f * x; }
__device__ __forceinline__ unsigned long long u64min(unsigned long long a, unsigned long long b) {
    return a < b ? a : b;
}

// ---------------- rigid 3x3 least squares + mask ----------------
__global__ void k_rigid(const float* __restrict__ xyz1, const float* __restrict__ vel1,
                        const float* __restrict__ fcc, const float* __restrict__ fcv,
                        float* __restrict__ out_vw)
{
    int t = blockIdx.x * blockDim.x + threadIdx.x;
    if (t >= BATCH * N1) return;
    int b = t / N1, n = t % N1;
    const float* cc = fcc + (size_t)t * KCC * 3;
    const float* cv = fcv + (size_t)t * KCC;
    double A00 = 1e-6, A01 = 0, A02 = 0, A11 = 1e-6, A12 = 0, A22 = 1e-6;
    double r0 = 0, r1 = 0, r2 = 0;
    for (int k = 0; k < KCC; k++) {
        double x = cc[k * 3 + 0], y = cc[k * 3 + 1], z = cc[k * 3 + 2];
        double inv = 1.0 / sqrt(x * x + y * y + z * z);
        x *= inv; y *= inv; z *= inv;
        A00 += x * x; A01 += x * y; A02 += x * z;
        A11 += y * y; A12 += y * z; A22 += z * z;
        double v = (double)cv[k];
        r0 += x * v; r1 += y * v; r2 += z * v;
    }
    double c00 = A11 * A22 - A12 * A12;
    double c01 = A01 * A22 - A12 * A02;
    double c02 = A01 * A12 - A11 * A02;
    double det = A00 * c00 - A01 * c01 + A02 * c02;
    double id = 1.0 / det;
    double v0 = (r0 * c00 - A01 * (r1 * A22 - A12 * r2) + A02 * (r1 * A12 - A11 * r2)) * id;
    double v1 = (A00 * (r1 * A22 - A12 * r2) - r0 * c01 + A02 * (A01 * r2 - r1 * A02)) * id;
    double v2 = (A00 * (A11 * r2 - r1 * A12) - A01 * (A01 * r2 - r1 * A02) + r0 * c02) * id;

    float fx = xyz1[(b * 3 + 0) * N1 + n];
    float fy = xyz1[(b * 3 + 1) * N1 + n];
    float fz = xyz1[(b * 3 + 2) * N1 + n];
    double inl = 1.0 / sqrt((double)fx * fx + (double)fy * fy + (double)fz * fz);
    double err = fabs((v0 * fx + v1 * fy + v2 * fz) * inl - (double)vel1[t]);
    bool m = (err <= 5.0);
    g_wf[t] = m ? 0.1f : 0.9f;
    g_wr[t] = m ? 0.9f : 0.1f;
    g_vw[t * 3 + 0] = (float)v0;
    g_vw[t * 3 + 1] = (float)v1;
    g_vw[t * 3 + 2] = (float)v2;
    if (out_vw) {
        out_vw[t * 3 + 0] = (float)v0;
        out_vw[t * 3 + 1] = (float)v1;
        out_vw[t * 3 + 2] = (float)v2;
    }
}

// ---------------- build weighted feature matrices F1,F2 ----------------
__global__ void k_feat(const float* __restrict__ xyz1, const float* __restrict__ xyz2,
                       const float* __restrict__ pts1, const float* __restrict__ pts2,
                       const float* __restrict__ wxyz_p, const float* __restrict__ wpts_p)
{
    float wx = *wxyz_p, wp = *wpts_p;
    const int total = BATCH * CP * N1;
    for (int e = blockIdx.x * blockDim.x + threadIdx.x; e < 2 * total;
         e += gridDim.x * blockDim.x) {
        int which = e / total;
        int r = e % total;
        int b = r / (CP * N1);
        int c = (r / N1) % CP;
        int n = r % N1;
        const float* xyz = which ? xyz2 : xyz1;
        const float* pts = which ? pts2 : pts1;
        float* F = which ? g_F2 : g_F1;
        float v = 0.f;
        if (c < 3) v = wx * xyz[(b * 3 + c) * N1 + n];
        else if (c < 67) v = wp * pts[(b * DD + (c - 3)) * N1 + n];
        F[r] = v;
    }
}

// ---------------- transposes to point-major ----------------
__global__ void k_trans(const float* __restrict__ pts1, const float* __restrict__ pts2,
                        const float* __restrict__ xyz1, const float* __restrict__ xyz2)
{
    const int tp = BATCH * DD * N1;
    const int tx3 = BATCH * 3 * N1;
    const int total = 2 * tp + 2 * tx3;
    for (int e = blockIdx.x * blockDim.x + threadIdx.x; e < total;
         e += gridDim.x * blockDim.x) {
        if (e < tp) {
            int b = e / (DD * N1), c = (e / N1) % DD, n = e % N1;
            g_p1T[((size_t)b * N1 + n) * DD + c] = pts1[e];
        } else if (e < 2 * tp) {
            int r = e - tp;
            int b = r / (DD * N1), c = (r / N1) % DD, n = r % N1;
            g_p2T[((size_t)b * N2 + n) * DD + c] = pts2[r];
        } else if (e < 2 * tp + tx3) {
            int r = e - 2 * tp;
            int b = r / (3 * N1), c = (r / N1) % 3, n = r % N1;
            g_x1T[(b * N1 + n) * 3 + c] = xyz1[r];
        } else {
            int r = e - 2 * tp - tx3;
            int b = r / (3 * N1), c = (r / N1) % 3, n = r % N1;
            g_x2T[(b * N2 + n) * 3 + c] = xyz2[r];
        }
    }
}

// ---------------- squared norms ----------------
__global__ void k_norm(int sel)
{
    int t = blockIdx.x * blockDim.x + threadIdx.x;
    if (t >= BATCH * 4096) return;
    int b = t / 4096, n = t % 4096;
    const float* F = (sel == 0) ? g_F1 : (sel == 1) ? g_F2 : g_CB;
    float* o = (sel == 0) ? g_nA : (sel == 1) ? g_nB : g_nC;
    float s = 0.f;
    #pragma unroll 8
    for (int c = 0; c < CP; c++) {
        float v = F[(b * CP + c) * 4096 + n];
        s += v * v;
    }
    o[t] = s;
}

// ---------------- comb features for second KNN ----------------
__global__ void k_comb()
{
    const int total = BATCH * CP * N1;
    for (int e = blockIdx.x * blockDim.x + threadIdx.x; e < total;
         e += gridDim.x * blockDim.x) {
        int b = e / (CP * N1);
        int c = (e / N1) % CP;
        int n = e % N1;
        float v = 0.f;
        if (c < 67) v = g_wf[b * N1 + n] * g_F1[e];
        else if (c < 70) v = g_wr[b * N1 + n] * g_vw[(b * N1 + n) * 3 + (c - 67)];
        g_CB[e] = v;
    }
}

// ---------------- distance matrix GEMM ----------------
__global__ void __launch_bounds__(256) k_dist(int sel)
{
    __shared__ float As[16][132];
    __shared__ float Bs[16][132];
    const float* FA = sel ? g_CB : g_F1;
    const float* FB = sel ? g_CB : g_F2;
    const float* nAv = sel ? g_nC : g_nA;
    const float* nBv = sel ? g_nC : g_nB;

    int b = blockIdx.z;
    int i0 = blockIdx.y * 128, j0 = blockIdx.x * 128;
    const float* Ab = FA + (size_t)b * CP * N1;
    const float* Bb = FB + (size_t)b * CP * N2;
    int tid = threadIdx.x;
    int tx = tid & 15, ty = tid >> 4;

    float acc[8][8];
    #pragma unroll
    for (int r = 0; r < 8; r++)
        #pragma unroll
        for (int s = 0; s < 8; s++) acc[r][s] = 0.f;

    for (int kc = 0; kc < CP; kc += 16) {
        #pragma unroll
        for (int l = 0; l < 8; l++) {
            int e = tid + l * 256;
            int r = e >> 7, c = e & 127;
            As[r][c] = Ab[(kc + r) * N1 + i0 + c];
            Bs[r][c] = Bb[(kc + r) * N2 + j0 + c];
        }
        __syncthreads();
        #pragma unroll
        for (int kk = 0; kk < 16; kk++) {
            float ar[8], br[8];
            #pragma unroll
            for (int u = 0; u < 4; u++) {
                ar[u] = As[kk][ty * 4 + u];
                ar[4 + u] = As[kk][64 + ty * 4 + u];
                br[u] = Bs[kk][tx * 4 + u];
                br[4 + u] = Bs[kk][64 + tx * 4 + u];
            }
            #pragma unroll
            for (int r = 0; r < 8; r++)
                #pragma unroll
                for (int s = 0; s < 8; s++) acc[r][s] += ar[r] * br[s];
        }
        __syncthreads();
    }
    float* drow = g_dist + (size_t)b * N1 * N2;
    #pragma unroll
    for (int r = 0; r < 8; r++) {
        int i = i0 + ((r < 4) ? (ty * 4 + r) : (64 + ty * 4 + (r - 4)));
        float ni = nAv[b * N1 + i];
        #pragma unroll
        for (int s = 0; s < 8; s++) {
            int j = j0 + ((s < 4) ? (tx * 4 + s) : (64 + tx * 4 + (s - 4)));
            float d = ni - 2.f * acc[r][s] + nBv[b * N2 + j];
            drow[(size_t)i * N2 + j] = fmaxf(d, 0.f);
        }
    }
}

// ---------------- top-K via incremental segment-min selection ----------------
__global__ void __launch_bounds__(128) k_topk(int sel)
{
    __shared__ unsigned long long keys[N2];     // 32 KB
    __shared__ unsigned long long segmin[256];  // 256 segments of 16
    __shared__ unsigned long long red[4];
    __shared__ int s_ext;
    int q = blockIdx.x;
    const float* row = g_dist + (size_t)q * N2;
    int* idxo = sel ? g_idx2 : g_idx1;
    int tid = threadIdx.x;

    #pragma unroll
    for (int s2 = 0; s2 < 2; s2++) {
        int seg = tid * 2 + s2;
        int basej = seg * 16;
        unsigned long long mn = ~0ull;
        #pragma unroll
        for (int i = 0; i < 4; i++) {
            float4 f = *(const float4*)(row + basej + i * 4);
            unsigned long long k0 = ((unsigned long long)__float_as_uint(f.x) << 32) | (unsigned)(basej + i * 4 + 0);
            unsigned long long k1 = ((unsigned long long)__float_as_uint(f.y) << 32) | (unsigned)(basej + i * 4 + 1);
            unsigned long long k2 = ((unsigned long long)__float_as_uint(f.z) << 32) | (unsigned)(basej + i * 4 + 2);
            unsigned long long k3 = ((unsigned long long)__float_as_uint(f.w) << 32) | (unsigned)(basej + i * 4 + 3);
            keys[basej + i * 4 + 0] = k0;
            keys[basej + i * 4 + 1] = k1;
            keys[basej + i * 4 + 2] = k2;
            keys[basej + i * 4 + 3] = k3;
            mn = u64min(mn, u64min(u64min(k0, k1), u64min(k2, k3)));
        }
        segmin[seg] = mn;
    }
    __syncthreads();

    for (int k = 0; k < KN; k++) {
        unsigned long long m = u64min(segmin[tid], segmin[tid + 128]);
        #pragma unroll
        for (int o = 16; o; o >>= 1) {
            unsigned long long v = __shfl_xor_sync(0xffffffffu, m, o);
            m = u64min(m, v);
        }
        if ((tid & 31) == 0) red[tid >> 5] = m;
        __syncthreads();
        if (tid == 0) {
            m = u64min(u64min(red[0], red[1]), u64min(red[2], red[3]));
            int j = (int)(unsigned)(m & 0xffffffffULL);
            idxo[q * KN + k] = j;
            keys[j] = ~0ull;
            s_ext = j;
        }
        __syncthreads();
        if (k < KN - 1) {
            int seg = s_ext >> 4;
            if (tid < 16) {
                unsigned long long v = keys[seg * 16 + tid];
                #pragma unroll
                for (int o = 8; o; o >>= 1) {
                    unsigned long long w = __shfl_xor_sync(0xffffu, v, o);
                    v = u64min(v, w);
                }
                if (tid == 0) segmin[seg] = v;
            }
            __syncthreads();
        }
    }
}

// ---------------- fused MLP: 8x8 register-tiled block GEMM ----------------
#define TNP 8
#define AW 132
#define OFF_W    0
#define OFF_A    (131 * AW)
#define OFF_B    (OFF_A + 131 * AW)
#define OFF_H2   (OFF_B + 128 * AW)
#define OFF_SW2  (OFF_H2 + 128 * 8)
#define OFF_SB2  (OFF_SW2 + 128 * 8)
#define OFF_PS   (OFF_SB2 + 128)
#define OFF_IDX  (OFF_PS + 16 * 128)
#define MLP_SMEM ((OFF_IDX + 128) * 4)

template<int KIN>
__device__ __forceinline__ void mm8x8(const float* __restrict__ A, const float* __restrict__ W,
                                      int tx, int ty, float (&acc)[8][8])
{
    #pragma unroll 4
    for (int kk = 0; kk < KIN; kk++) {
        float4 a0 = *(const float4*)(A + kk * AW + tx * 8);
        float4 a1 = *(const float4*)(A + kk * AW + tx * 8 + 4);
        float4 w0 = *(const float4*)(W + kk * AW + ty * 8);
        float4 w1 = *(const float4*)(W + kk * AW + ty * 8 + 4);
        float a[8] = {a0.x, a0.y, a0.z, a0.w, a1.x, a1.y, a1.z, a1.w};
        float w[8] = {w0.x, w0.y, w0.z, w0.w, w1.x, w1.y, w1.z, w1.w};
        #pragma unroll
        for (int u = 0; u < 8; u++)
            #pragma unroll
            for (int v = 0; v < 8; v++)
                acc[u][v] += w[u] * a[v];
    }
}

__global__ void __launch_bounds__(256) k_mlp(
    const float* __restrict__ w0g, const float* __restrict__ b0g,
    const float* __restrict__ w1g, const float* __restrict__ b1g,
    const float* __restrict__ w2g, const float* __restrict__ b2g,
    const float* __restrict__ n1w0, const float* __restrict__ n1b0,
    const float* __restrict__ n1w1, const float* __restrict__ n1b1,
    const float* __restrict__ n1w2, const float* __restrict__ n1b2)
{
    extern __shared__ float sm[];
    float* Wsm = sm + OFF_W;
    float* Abuf = sm + OFF_A;
    float* Bbuf = sm + OFF_B;
    float* h2s = sm + OFF_H2;
    float* sw2 = sm + OFF_SW2;
    float* sb2 = sm + OFF_SB2;
    float* ps  = sm + OFF_PS;
    int* idxs = (int*)(sm + OFF_IDX);

    int tid = threadIdx.x;
    int tx = tid & 15, ty = tid >> 4;
    int base = blockIdx.x * TNP;

    if (tid < 128) {
        idxs[tid] = g_idx1[base * KN + tid];
        sw2[tid] = n1w2[tid];
        sw2[tid + 128] = n1w2[tid + 128];
        sw2[tid + 256] = n1w2[tid + 256];
        sw2[tid + 384] = n1w2[tid + 384];
        sw2[tid + 512] = n1w2[tid + 512];
        sw2[tid + 640] = n1w2[tid + 640];
        sw2[tid + 768] = n1w2[tid + 768];
        sw2[tid + 896] = n1w2[tid + 896];
        sb2[tid] = n1b2[tid];
    }
    __syncthreads();

    // stage A [131][128]: rows 0-63 p1, 64-127 gathered p2, 128-130 dxyz
    for (int e = tid; e < 131 * 128; e += 256) {
        int i = e >> 7, col = e & 127;
        int tn = col >> 4;
        int pt = base + tn;
        int b = pt >> 12;
        int j = idxs[col];
        float v;
        if (i < 64) v = g_p1T[(size_t)pt * DD + i];
        else if (i < 128) v = g_p2T[((size_t)b * N2 + j) * DD + (i - 64)];
        else v = g_x2T[(b * N2 + j) * 3 + (i - 128)] - g_x1T[pt * 3 + (i - 128)];
        Abuf[i * AW + col] = v;
    }
    // stage W0 transposed [in 131][out 128]
    for (int e = tid; e < 128 * 131; e += 256) {
        int i = e % 131, c = e / 131;
        Wsm[i * AW + c] = w0g[e];
    }
    __syncthreads();

    // weight-net 1 (3->8->8) per column -> h2s[col][8]
    if (tid < 128) {
        int col = tid;
        float dx0 = Abuf[128 * AW + col];
        float dx1 = Abuf[129 * AW + col];
        float dx2 = Abuf[130 * AW + col];
        float h[8];
        #pragma unroll
        for (int j = 0; j < 8; j++) {
            float s = n1w0[j * 3 + 0] * dx0 + n1w0[j * 3 + 1] * dx1 + n1w0[j * 3 + 2] * dx2 + n1b0[j];
            h[j] = fmaxf(s, 0.f);
        }
        #pragma unroll
        for (int j = 0; j < 8; j++) {
            float s = n1b1[j];
            #pragma unroll
            for (int m = 0; m < 8; m++) s += n1w1[j * 8 + m] * h[m];
            h2s[col * 8 + j] = fmaxf(s, 0.f);
        }
    }
    __syncthreads();

    float bias0[8], bias1[8], bias2[8];
    #pragma unroll
    for (int u = 0; u < 8; u++) {
        bias0[u] = b0g[ty * 8 + u];
        bias1[u] = b1g[ty * 8 + u];
        bias2[u] = b2g[ty * 8 + u];
    }

    float acc[8][8];

    // ---- layer 1: 131 -> 128, leaky ----
    #pragma unroll
    for (int u = 0; u < 8; u++)
        #pragma unroll
        for (int v = 0; v < 8; v++) acc[u][v] = bias0[u];
    mm8x8<131>(Abuf, Wsm, tx, ty, acc);
    #pragma unroll
    for (int u = 0; u < 8; u++) {
        float4 o0, o1;
        o0.x = leakyf(acc[u][0]); o0.y = leakyf(acc[u][1]);
        o0.z = leakyf(acc[u][2]); o0.w = leakyf(acc[u][3]);
        o1.x = leakyf(acc[u][4]); o1.y = leakyf(acc[u][5]);
        o1.z = leakyf(acc[u][6]); o1.w = leakyf(acc[u][7]);
        *(float4*)(Bbuf + (ty * 8 + u) * AW + tx * 8) = o0;
        *(float4*)(Bbuf + (ty * 8 + u) * AW + tx * 8 + 4) = o1;
    }
    __syncthreads();

    // stage W1
    for (int e = tid; e < 128 * 128; e += 256) {
        int i = e & 127, c = e >> 7;
        Wsm[i * AW + c] = w1g[e];
    }
    __syncthreads();

    // ---- layer 2: 128 -> 128, leaky (write into Abuf rows 0..127) ----
    #pragma unroll
    for (int u = 0; u < 8; u++)
        #pragma unroll
        for (int v = 0; v < 8; v++) acc[u][v] = bias1[u];
    mm8x8<128>(Bbuf, Wsm, tx, ty, acc);
    #pragma unroll
    for (int u = 0; u < 8; u++) {
        float4 o0, o1;
        o0.x = leakyf(acc[u][0]); o0.y = leakyf(acc[u][1]);
        o0.z = leakyf(acc[u][2]); o0.w = leakyf(acc[u][3]);
        o1.x = leakyf(acc[u][4]); o1.y = leakyf(acc[u][5]);
        o1.z = leakyf(acc[u][6]); o1.w = leakyf(acc[u][7]);
        *(float4*)(Abuf + (ty * 8 + u) * AW + tx * 8) = o0;
        *(float4*)(Abuf + (ty * 8 + u) * AW + tx * 8 + 4) = o1;
    }
    __syncthreads();

    // stage W2
    for (int e = tid; e < 128 * 128; e += 256) {
        int i = e & 127, c = e >> 7;
        Wsm[i * AW + c] = w2g[e];
    }
    __syncthreads();

    // ---- S matrix: s[col][c] = relu(b2[c] + sum_j w2[c][j]*h2[col][j]) -> Bbuf ----
    {
        int col = tid >> 1, chalf = tid & 1;
        float hj[8];
        #pragma unroll
        for (int j = 0; j < 8; j++) hj[j] = h2s[col * 8 + j];
        #pragma unroll 4
        for (int cc = 0; cc < 64; cc++) {
            int c = chalf * 64 + cc;
            float s = sb2[c];
            #pragma unroll
            for (int j = 0; j < 8; j++) s += sw2[c * 8 + j] * hj[j];
            Bbuf[col * AW + c] = fmaxf(s, 0.f);
        }
    }

    // ---- layer 3: 128 -> 128 ----
    #pragma unroll
    for (int u = 0; u < 8; u++)
        #pragma unroll
        for (int v = 0; v < 8; v++) acc[u][v] = bias2[u];
    mm8x8<128>(Abuf, Wsm, tx, ty, acc);
    __syncthreads();   // S writes visible

    // ---- epilogue: partial[u] = sum_v S[col_v][c_u] * leaky(acc[u][v]) ----
    {
        float partial[8];
        #pragma unroll
        for (int u = 0; u < 8; u++) partial[u] = 0.f;
        #pragma unroll
        for (int v = 0; v < 8; v++) {
            int col = tx * 8 + v;
            float4 s0 = *(const float4*)(Bbuf + col * AW + ty * 8);
            float4 s1 = *(const float4*)(Bbuf + col * AW + ty * 8 + 4);
            float s[8] = {s0.x, s0.y, s0.z, s0.w, s1.x, s1.y, s1.z, s1.w};
            #pragma unroll
            for (int u = 0; u < 8; u++) partial[u] += s[u] * leakyf(acc[u][v]);
        }
        #pragma unroll
        for (int u = 0; u < 8; u++) ps[tx * 128 + ty * 8 + u] = partial[u];
    }
    __syncthreads();
    for (int e = tid; e < 1024; e += 256) {
        int tn = e >> 7, c = e & 127;
        g_p2p[(size_t)(base + tn) * CO + c] = ps[(2 * tn) * 128 + c] + ps[(2 * tn + 1) * 128 + c];
    }
}

// ---------------- patch aggregation ----------------
__global__ void __launch_bounds__(128) k_patch(
    const float* __restrict__ n2w0, const float* __restrict__ n2b0,
    const float* __restrict__ n2w1, const float* __restrict__ n2b1,
    const float* __restrict__ n2w2, const float* __restrict__ n2b2,
    float* __restrict__ out)
{
    __shared__ float h2s[16][8];
    __shared__ int js[16];
    int q = blockIdx.x;
    int b = q / N1, n = q % N1;
    int tid = threadIdx.x;
    if (tid < 16) {
        int j = g_idx2[q * KN + tid];
        js[tid] = j;
        float dx0 = g_x1T[(b * N1 + j) * 3 + 0] - g_x1T[q * 3 + 0];
        float dx1 = g_x1T[(b * N1 + j) * 3 + 1] - g_x1T[q * 3 + 1];
        float dx2 = g_x1T[(b * N1 + j) * 3 + 2] - g_x1T[q * 3 + 2];
        float h[8];
        #pragma unroll
        for (int jj = 0; jj < 8; jj++) {
            float s = n2w0[jj * 3 + 0] * dx0 + n2w0[jj * 3 + 1] * dx1 + n2w0[jj * 3 + 2] * dx2 + n2b0[jj];
            h[jj] = fmaxf(s, 0.f);
        }
        #pragma unroll
        for (int jj = 0; jj < 8; jj++) {
            float s = n2b1[jj];
            #pragma unroll
            for (int m = 0; m < 8; m++) s += n2w1[jj * 8 + m] * h[m];
            h2s[tid][jj] = fmaxf(s, 0.f);
        }
    }
    __syncthreads();
    int c = tid;
    float w2r[8];
    #pragma unroll
    for (int j = 0; j < 8; j++) w2r[j] = n2w2[c * 8 + j];
    float bc = n2b2[c];
    float acc = 0.f;
    #pragma unroll
    for (int k = 0; k < KN; k++) {
        float s = bc;
        #pragma unroll
        for (int j = 0; j < 8; j++) s += w2r[j] * h2s[k][j];
        s = fmaxf(s, 0.f);
        acc += s * g_p2p[((size_t)b * N1 + js[k]) * CO + c];
    }
    out[(size_t)b * CO * N1 + (size_t)c * N1 + n] = acc;
}

// ---------------- launch ----------------
extern "C" void kernel_launch(void* const* d_in, const int* in_sizes, int n_in,
                              void* d_out, int out_size)
{
    int s = (n_in >= 31) ? 0 : -2;
    const float* xyz1 = (const float*)d_in[0];
    const float* xyz2 = (const float*)d_in[1];
    const float* pts1 = (const float*)d_in[2];
    const float* pts2 = (const float*)d_in[3];
    const float* vel1 = (const float*)d_in[4];
    const float* fcc  = (const float*)d_in[8 + s];
    const float* fcv  = (const float*)d_in[9 + s];
    const float* wxyz = (const float*)d_in[10 + s];
    const float* wpts = (const float*)d_in[12 + s];
    const float* mw0 = (const float*)d_in[13 + s];
    const float* mb0 = (const float*)d_in[14 + s];
    const float* mw1 = (const float*)d_in[15 + s];
    const float* mb1 = (const float*)d_in[16 + s];
    const float* mw2 = (const float*)d_in[17 + s];
    const float* mb2 = (const float*)d_in[18 + s];
    const float* n1w0 = (const float*)d_in[19 + s];
    const float* n1b0 = (const float*)d_in[20 + s];
    const float* n2w0 = (const float*)d_in[21 + s];
    const float* n2b0 = (const float*)d_in[22 + s];
    const float* n1w1 = (const float*)d_in[23 + s];
    const float* n1b1 = (const float*)d_in[24 + s];
    const float* n2w1 = (const float*)d_in[25 + s];
    const float* n2b1 = (const float*)d_in[26 + s];
    const float* n1w2 = (const float*)d_in[27 + s];
    const float* n1b2 = (const float*)d_in[28 + s];
    const float* n2w2 = (const float*)d_in[29 + s];
    const float* n2b2 = (const float*)d_in[30 + s];

    float* out = (float*)d_out;
    const int patch_elems = BATCH * CO * N1;
    const int vw_elems = BATCH * N1 * 3;
    float* out_vw = (out_size >= patch_elems + vw_elems) ? (out + patch_elems) : nullptr;

    cudaFuncSetAttribute(k_mlp, cudaFuncAttributeMaxDynamicSharedMemorySize, (int)MLP_SMEM);

    k_rigid<<<(BATCH * N1 + 127) / 128, 128>>>(xyz1, vel1, fcc, fcv, out_vw);
    k_feat<<<(2 * BATCH * CP * N1 + 255) / 256, 256>>>(xyz1, xyz2, pts1, pts2, wxyz, wpts);
    k_trans<<<(2 * BATCH * DD * N1 + 2 * BATCH * 3 * N1 + 255) / 256, 256>>>(pts1, pts2, xyz1, xyz2);
    k_norm<<<(BATCH * 4096 + 127) / 128, 128>>>(0);
    k_norm<<<(BATCH * 4096 + 127) / 128, 128>>>(1);
    k_comb<<<(BATCH * CP * N1 + 255) / 256, 256>>>();
    k_norm<<<(BATCH * 4096 + 127) / 128, 128>>>(2);

    dim3 gg(N2 / 128, N1 / 128, BATCH);
    k_dist<<<gg, 256>>>(0);
    k_topk<<<BATCH * N1, 128>>>(0);

    k_mlp<<<(BATCH * N1) / TNP, 256, MLP_SMEM>>>(mw0, mb0, mw1, mb1, mw2, mb2,
                                                 n1w0, n1b0, n1w1, n1b1, n1w2, n1b2);

    k_dist<<<gg, 256>>>(1);
    k_topk<<<BATCH * N1, 128>>>(1);

    k_patch<<<BATCH * N1, 128>>>(n2w0, n2b0, n2w1, n2b1, n2w2, n2b2, out);
}

// round 4
// speedup vs baseline: 1.3406x; 1.0179x over previous
#include <cuda_runtime.h>
#include <math.h>

#define BATCH 2
#define N1 4096
#define N2 4096
#define DD 64
#define KN 16
#define KCC 8
#define CP 80      // padded feature channels (67 / 70 used)
#define CO 128

// ---------------- scratch (static device memory; no runtime alloc) ----------------
__device__ float g_dist[(size_t)BATCH * N1 * N2];        // 134 MB
__device__ float g_F1[BATCH * CP * N1];
__device__ float g_F2[BATCH * CP * N2];
__device__ float g_CB[BATCH * CP * N1];
__device__ float g_nA[BATCH * N1];
__device__ float g_nB[BATCH * N2];
__device__ float g_nC[BATCH * N1];
__device__ int   g_idx1[BATCH * N1 * KN];
__device__ int   g_idx2[BATCH * N1 * KN];
__device__ float g_vw[BATCH * N1 * 3];
__device__ float g_wf[BATCH * N1];
__device__ float g_wr[BATCH * N1];
__device__ float g_p1T[BATCH * N1 * DD];
__device__ float g_p2T[BATCH * N2 * DD];
__device__ float g_x1T[BATCH * N1 * 3];
__device__ float g_x2T[BATCH * N2 * 3];
__device__ float g_p2p[(size_t)BATCH * N1 * CO];

__device__ __forceinline__ float leakyf(float x) { return x >= 0.f ? x : 0.1f * x; }
__device__ __forceinline__ unsigned long long u64min(unsigned long long a, unsigned long long b) {
    return a < b ? a : b;
}

// ---- packed f32x2 helpers (FFMA2 path: double-rate fp32 on sm_103a) ----
__device__ __forceinline__ unsigned long long bcast2(float x) {
    unsigned long long r;
    asm("mov.b64 %0, {%1,%1};" : "=l"(r) : "f"(x));
    return r;
}
__device__ __forceinline__ unsigned long long fma2(unsigned long long a, unsigned long long b,
                                                   unsigned long long c) {
    unsigned long long d;
    asm("fma.rn.f32x2 %0, %1, %2, %3;" : "=l"(d) : "l"(a), "l"(b), "l"(c));
    return d;
}
__device__ __forceinline__ void unp2(unsigned long long v, float& lo, float& hi) {
    asm("mov.b64 {%0,%1}, %2;" : "=f"(lo), "=f"(hi) : "l"(v));
}

// ---------------- rigid 3x3 least squares + mask ----------------
__global__ void k_rigid(const float* __restrict__ xyz1, const float* __restrict__ vel1,
                        const float* __restrict__ fcc, const float* __restrict__ fcv,
                        float* __restrict__ out_vw)
{
    int t = blockIdx.x * blockDim.x + threadIdx.x;
    if (t >= BATCH * N1) return;
    int b = t / N1, n = t % N1;
    const float* cc = fcc + (size_t)t * KCC * 3;
    const float* cv = fcv + (size_t)t * KCC;
    double A00 = 1e-6, A01 = 0, A02 = 0, A11 = 1e-6, A12 = 0, A22 = 1e-6;
    double r0 = 0, r1 = 0, r2 = 0;
    for (int k = 0; k < KCC; k++) {
        double x = cc[k * 3 + 0], y = cc[k * 3 + 1], z = cc[k * 3 + 2];
        double inv = 1.0 / sqrt(x * x + y * y + z * z);
        x *= inv; y *= inv; z *= inv;
        A00 += x * x; A01 += x * y; A02 += x * z;
        A11 += y * y; A12 += y * z; A22 += z * z;
        double v = (double)cv[k];
        r0 += x * v; r1 += y * v; r2 += z * v;
    }
    double c00 = A11 * A22 - A12 * A12;
    double c01 = A01 * A22 - A12 * A02;
    double c02 = A01 * A12 - A11 * A02;
    double det = A00 * c00 - A01 * c01 + A02 * c02;
    double id = 1.0 / det;
    double v0 = (r0 * c00 - A01 * (r1 * A22 - A12 * r2) + A02 * (r1 * A12 - A11 * r2)) * id;
    double v1 = (A00 * (r1 * A22 - A12 * r2) - r0 * c01 + A02 * (A01 * r2 - r1 * A02)) * id;
    double v2 = (A00 * (A11 * r2 - r1 * A12) - A01 * (A01 * r2 - r1 * A02) + r0 * c02) * id;

    float fx = xyz1[(b * 3 + 0) * N1 + n];
    float fy = xyz1[(b * 3 + 1) * N1 + n];
    float fz = xyz1[(b * 3 + 2) * N1 + n];
    double inl = 1.0 / sqrt((double)fx * fx + (double)fy * fy + (double)fz * fz);
    double err = fabs((v0 * fx + v1 * fy + v2 * fz) * inl - (double)vel1[t]);
    bool m = (err <= 5.0);
    g_wf[t] = m ? 0.1f : 0.9f;
    g_wr[t] = m ? 0.9f : 0.1f;
    g_vw[t * 3 + 0] = (float)v0;
    g_vw[t * 3 + 1] = (float)v1;
    g_vw[t * 3 + 2] = (float)v2;
    if (out_vw) {
        out_vw[t * 3 + 0] = (float)v0;
        out_vw[t * 3 + 1] = (float)v1;
        out_vw[t * 3 + 2] = (float)v2;
    }
}

// ---------------- fused: weighted feature build + transposes ----------------
__global__ void k_prep(const float* __restrict__ xyz1, const float* __restrict__ xyz2,
                       const float* __restrict__ pts1, const float* __restrict__ pts2,
                       const float* __restrict__ wxyz_p, const float* __restrict__ wpts_p)
{
    float wx = *wxyz_p, wp = *wpts_p;
    const int totalF = BATCH * CP * N1;          // per F matrix
    const int tp = BATCH * DD * N1;              // per points transpose
    const int tx3 = BATCH * 3 * N1;              // per xyz transpose
    const int total = 2 * totalF + 2 * tp + 2 * tx3;
    for (int e = blockIdx.x * blockDim.x + threadIdx.x; e < total;
         e += gridDim.x * blockDim.x) {
        if (e < 2 * totalF) {
            int which = e / totalF;
            int r = e % totalF;
            int b = r / (CP * N1);
            int c = (r / N1) % CP;
            int n = r % N1;
            const float* xyz = which ? xyz2 : xyz1;
            const float* pts = which ? pts2 : pts1;
            float* F = which ? g_F2 : g_F1;
            float v = 0.f;
            if (c < 3) v = wx * xyz[(b * 3 + c) * N1 + n];
            else if (c < 67) v = wp * pts[(b * DD + (c - 3)) * N1 + n];
            F[r] = v;
        } else if (e < 2 * totalF + 2 * tp) {
            int r = e - 2 * totalF;
            if (r < tp) {
                int b = r / (DD * N1), c = (r / N1) % DD, n = r % N1;
                g_p1T[((size_t)b * N1 + n) * DD + c] = pts1[r];
            } else {
                r -= tp;
                int b = r / (DD * N1), c = (r / N1) % DD, n = r % N1;
                g_p2T[((size_t)b * N2 + n) * DD + c] = pts2[r];
            }
        } else {
            int r = e - 2 * totalF - 2 * tp;
            if (r < tx3) {
                int b = r / (3 * N1), c = (r / N1) % 3, n = r % N1;
                g_x1T[(b * N1 + n) * 3 + c] = xyz1[r];
            } else {
                r -= tx3;
                int b = r / (3 * N1), c = (r / N1) % 3, n = r % N1;
                g_x2T[(b * N2 + n) * 3 + c] = xyz2[r];
            }
        }
    }
}

// ---------------- all three squared norms in one launch ----------------
__global__ void k_norms()
{
    int t = blockIdx.x * blockDim.x + threadIdx.x;
    if (t >= BATCH * 4096) return;
    int b = t / 4096, n = t % 4096;
    float sA = 0.f, sB = 0.f;
    #pragma unroll 8
    for (int c = 0; c < CP; c++) {
        float a = g_F1[(b * CP + c) * 4096 + n];
        float bb = g_F2[(b * CP + c) * 4096 + n];
        sA += a * a;
        sB += bb * bb;
    }
    g_nA[t] = sA;
    g_nB[t] = sB;
    float wf = g_wf[t], wr = g_wr[t];
    float v0 = g_vw[t * 3 + 0], v1 = g_vw[t * 3 + 1], v2 = g_vw[t * 3 + 2];
    g_nC[t] = wf * wf * sA + wr * wr * (v0 * v0 + v1 * v1 + v2 * v2);
}

// ---------------- comb features for second KNN ----------------
__global__ void k_comb()
{
    const int total = BATCH * CP * N1;
    for (int e = blockIdx.x * blockDim.x + threadIdx.x; e < total;
         e += gridDim.x * blockDim.x) {
        int b = e / (CP * N1);
        int c = (e / N1) % CP;
        int n = e % N1;
        float v = 0.f;
        if (c < 67) v = g_wf[b * N1 + n] * g_F1[e];
        else if (c < 70) v = g_wr[b * N1 + n] * g_vw[(b * N1 + n) * 3 + (c - 67)];
        g_CB[e] = v;
    }
}

// ---------------- distance matrix GEMM (FFMA2 packed) ----------------
__global__ void __launch_bounds__(256) k_dist(int sel)
{
    __shared__ float As[16][132];
    __shared__ float Bs[16][132];
    const float* FA = sel ? g_CB : g_F1;
    const float* FB = sel ? g_CB : g_F2;
    const float* nAv = sel ? g_nC : g_nA;
    const float* nBv = sel ? g_nC : g_nB;

    int b = blockIdx.z;
    int i0 = blockIdx.y * 128, j0 = blockIdx.x * 128;
    const float* Ab = FA + (size_t)b * CP * N1;
    const float* Bb = FB + (size_t)b * CP * N2;
    int tid = threadIdx.x;
    int tx = tid & 15, ty = tid >> 4;

    unsigned long long acc2[8][4];
    #pragma unroll
    for (int r = 0; r < 8; r++)
        #pragma unroll
        for (int sp = 0; sp < 4; sp++) acc2[r][sp] = 0ull;

    for (int kc = 0; kc < CP; kc += 16) {
        #pragma unroll
        for (int l = 0; l < 8; l++) {
            int e = tid + l * 256;
            int r = e >> 7, c = e & 127;
            As[r][c] = Ab[(kc + r) * N1 + i0 + c];
            Bs[r][c] = Bb[(kc + r) * N2 + j0 + c];
        }
        __syncthreads();
        #pragma unroll
        for (int kk = 0; kk < 16; kk++) {
            float4 a0 = *(const float4*)&As[kk][ty * 4];
            float4 a1 = *(const float4*)&As[kk][64 + ty * 4];
            ulonglong2 b0 = *(const ulonglong2*)&Bs[kk][tx * 4];
            ulonglong2 b1 = *(const ulonglong2*)&Bs[kk][64 + tx * 4];
            unsigned long long br[4] = {b0.x, b0.y, b1.x, b1.y};
            unsigned long long aa[8];
            aa[0] = bcast2(a0.x); aa[1] = bcast2(a0.y); aa[2] = bcast2(a0.z); aa[3] = bcast2(a0.w);
            aa[4] = bcast2(a1.x); aa[5] = bcast2(a1.y); aa[6] = bcast2(a1.z); aa[7] = bcast2(a1.w);
            #pragma unroll
            for (int r = 0; r < 8; r++)
                #pragma unroll
                for (int sp = 0; sp < 4; sp++)
                    acc2[r][sp] = fma2(aa[r], br[sp], acc2[r][sp]);
        }
        __syncthreads();
    }
    float* drow = g_dist + (size_t)b * N1 * N2;
    #pragma unroll
    for (int r = 0; r < 8; r++) {
        int i = i0 + ((r < 4) ? (ty * 4 + r) : (64 + ty * 4 + (r - 4)));
        float ni = nAv[b * N1 + i];
        #pragma unroll
        for (int sp = 0; sp < 4; sp++) {
            float d0, d1;
            unp2(acc2[r][sp], d0, d1);
            int jj = j0 + ((sp < 2) ? (tx * 4 + sp * 2) : (64 + tx * 4 + (sp - 2) * 2));
            float e0 = ni - 2.f * d0 + nBv[b * N2 + jj];
            float e1 = ni - 2.f * d1 + nBv[b * N2 + jj + 1];
            drow[(size_t)i * N2 + jj] = fmaxf(e0, 0.f);
            drow[(size_t)i * N2 + jj + 1] = fmaxf(e1, 0.f);
        }
    }
}

// ---------------- top-K via incremental segment-min selection ----------------
__global__ void __launch_bounds__(128) k_topk(int sel)
{
    __shared__ unsigned long long keys[N2];     // 32 KB
    __shared__ unsigned long long segmin[256];  // 256 segments of 16
    __shared__ unsigned long long red[4];
    __shared__ int s_ext;
    int q = blockIdx.x;
    const float* row = g_dist + (size_t)q * N2;
    int* idxo = sel ? g_idx2 : g_idx1;
    int tid = threadIdx.x;

    #pragma unroll
    for (int s2 = 0; s2 < 2; s2++) {
        int seg = tid * 2 + s2;
        int basej = seg * 16;
        unsigned long long mn = ~0ull;
        #pragma unroll
        for (int i = 0; i < 4; i++) {
            float4 f = *(const float4*)(row + basej + i * 4);
            unsigned long long k0 = ((unsigned long long)__float_as_uint(f.x) << 32) | (unsigned)(basej + i * 4 + 0);
            unsigned long long k1 = ((unsigned long long)__float_as_uint(f.y) << 32) | (unsigned)(basej + i * 4 + 1);
            unsigned long long k2 = ((unsigned long long)__float_as_uint(f.z) << 32) | (unsigned)(basej + i * 4 + 2);
            unsigned long long k3 = ((unsigned long long)__float_as_uint(f.w) << 32) | (unsigned)(basej + i * 4 + 3);
            keys[basej + i * 4 + 0] = k0;
            keys[basej + i * 4 + 1] = k1;
            keys[basej + i * 4 + 2] = k2;
            keys[basej + i * 4 + 3] = k3;
            mn = u64min(mn, u64min(u64min(k0, k1), u64min(k2, k3)));
        }
        segmin[seg] = mn;
    }
    __syncthreads();

    for (int k = 0; k < KN; k++) {
        unsigned long long m = u64min(segmin[tid], segmin[tid + 128]);
        #pragma unroll
        for (int o = 16; o; o >>= 1) {
            unsigned long long v = __shfl_xor_sync(0xffffffffu, m, o);
            m = u64min(m, v);
        }
        if ((tid & 31) == 0) red[tid >> 5] = m;
        __syncthreads();
        if (tid == 0) {
            m = u64min(u64min(red[0], red[1]), u64min(red[2], red[3]));
            int j = (int)(unsigned)(m & 0xffffffffULL);
            idxo[q * KN + k] = j;
            keys[j] = ~0ull;
            s_ext = j;
        }
        __syncthreads();
        if (k < KN - 1) {
            int seg = s_ext >> 4;
            if (tid < 16) {
                unsigned long long v = keys[seg * 16 + tid];
                #pragma unroll
                for (int o = 8; o; o >>= 1) {
                    unsigned long long w = __shfl_xor_sync(0xffffu, v, o);
                    v = u64min(v, w);
                }
                if (tid == 0) segmin[seg] = v;
            }
            __syncthreads();
        }
    }
}

// ---------------- fused MLP: 8x8 register-tiled block GEMM (FFMA2 packed) ----------------
#define TNP 8
#define AW 132
#define OFF_W    0
#define OFF_A    (131 * AW)
#define OFF_B    (OFF_A + 131 * AW)
#define OFF_H2   (OFF_B + 128 * AW)
#define OFF_SW2  (OFF_H2 + 128 * 8)
#define OFF_SB2  (OFF_SW2 + 128 * 8)
#define OFF_PS   (OFF_SB2 + 128)
#define OFF_IDX  (OFF_PS + 16 * 128)
#define MLP_SMEM ((OFF_IDX + 128) * 4)

template<int KIN>
__device__ __forceinline__ void mm8x8p(const float* __restrict__ A, const float* __restrict__ W,
                                       int tx, int ty, unsigned long long (&acc)[8][4])
{
    #pragma unroll 4
    for (int kk = 0; kk < KIN; kk++) {
        ulonglong2 a01 = *(const ulonglong2*)(A + kk * AW + tx * 8);
        ulonglong2 a23 = *(const ulonglong2*)(A + kk * AW + tx * 8 + 4);
        float4 w0 = *(const float4*)(W + kk * AW + ty * 8);
        float4 w1 = *(const float4*)(W + kk * AW + ty * 8 + 4);
        unsigned long long av[4] = {a01.x, a01.y, a23.x, a23.y};
        unsigned long long wb[8];
        wb[0] = bcast2(w0.x); wb[1] = bcast2(w0.y); wb[2] = bcast2(w0.z); wb[3] = bcast2(w0.w);
        wb[4] = bcast2(w1.x); wb[5] = bcast2(w1.y); wb[6] = bcast2(w1.z); wb[7] = bcast2(w1.w);
        #pragma unroll
        for (int u = 0; u < 8; u++)
            #pragma unroll
            for (int vp = 0; vp < 4; vp++)
                acc[u][vp] = fma2(wb[u], av[vp], acc[u][vp]);
    }
}

__device__ __forceinline__ void store_leaky8(float* dst, const unsigned long long (&acc)[8][4],
                                             int u)
{
    float x[8];
    unp2(acc[u][0], x[0], x[1]);
    unp2(acc[u][1], x[2], x[3]);
    unp2(acc[u][2], x[4], x[5]);
    unp2(acc[u][3], x[6], x[7]);
    float4 o0, o1;
    o0.x = leakyf(x[0]); o0.y = leakyf(x[1]); o0.z = leakyf(x[2]); o0.w = leakyf(x[3]);
    o1.x = leakyf(x[4]); o1.y = leakyf(x[5]); o1.z = leakyf(x[6]); o1.w = leakyf(x[7]);
    *(float4*)dst = o0;
    *(float4*)(dst + 4) = o1;
}

__global__ void __launch_bounds__(256) k_mlp(
    const float* __restrict__ w0g, const float* __restrict__ b0g,
    const float* __restrict__ w1g, const float* __restrict__ b1g,
    const float* __restrict__ w2g, const float* __restrict__ b2g,
    const float* __restrict__ n1w0, const float* __restrict__ n1b0,
    const float* __restrict__ n1w1, const float* __restrict__ n1b1,
    const float* __restrict__ n1w2, const float* __restrict__ n1b2)
{
    extern __shared__ float sm[];
    float* Wsm = sm + OFF_W;
    float* Abuf = sm + OFF_A;
    float* Bbuf = sm + OFF_B;
    float* h2s = sm + OFF_H2;
    float* sw2 = sm + OFF_SW2;
    float* sb2 = sm + OFF_SB2;
    float* ps  = sm + OFF_PS;
    int* idxs = (int*)(sm + OFF_IDX);

    int tid = threadIdx.x;
    int tx = tid & 15, ty = tid >> 4;
    int base = blockIdx.x * TNP;

    if (tid < 128) {
        idxs[tid] = g_idx1[base * KN + tid];
        #pragma unroll
        for (int r = 0; r < 8; r++) sw2[tid + 128 * r] = n1w2[tid + 128 * r];
        sb2[tid] = n1b2[tid];
    }
    __syncthreads();

    // stage A [131][128]
    for (int e = tid; e < 131 * 128; e += 256) {
        int i = e >> 7, col = e & 127;
        int tn = col >> 4;
        int pt = base + tn;
        int b = pt >> 12;
        int j = idxs[col];
        float v;
        if (i < 64) v = g_p1T[(size_t)pt * DD + i];
        else if (i < 128) v = g_p2T[((size_t)b * N2 + j) * DD + (i - 64)];
        else v = g_x2T[(b * N2 + j) * 3 + (i - 128)] - g_x1T[pt * 3 + (i - 128)];
        Abuf[i * AW + col] = v;
    }
    // stage W0 transposed [in 131][out 128]
    for (int e = tid; e < 128 * 131; e += 256) {
        int i = e % 131, c = e / 131;
        Wsm[i * AW + c] = w0g[e];
    }
    __syncthreads();

    // weight-net 1 (3->8->8) per column -> h2s[col][8]
    if (tid < 128) {
        int col = tid;
        float dx0 = Abuf[128 * AW + col];
        float dx1 = Abuf[129 * AW + col];
        float dx2 = Abuf[130 * AW + col];
        float h[8];
        #pragma unroll
        for (int j = 0; j < 8; j++) {
            float s = n1w0[j * 3 + 0] * dx0 + n1w0[j * 3 + 1] * dx1 + n1w0[j * 3 + 2] * dx2 + n1b0[j];
            h[j] = fmaxf(s, 0.f);
        }
        #pragma unroll
        for (int j = 0; j < 8; j++) {
            float s = n1b1[j];
            #pragma unroll
            for (int m = 0; m < 8; m++) s += n1w1[j * 8 + m] * h[m];
            h2s[col * 8 + j] = fmaxf(s, 0.f);
        }
    }
    __syncthreads();

    unsigned long long bias0[8], bias1[8], bias2[8];
    #pragma unroll
    for (int u = 0; u < 8; u++) {
        bias0[u] = bcast2(b0g[ty * 8 + u]);
        bias1[u] = bcast2(b1g[ty * 8 + u]);
        bias2[u] = bcast2(b2g[ty * 8 + u]);
    }

    unsigned long long acc[8][4];

    // ---- layer 1: 131 -> 128, leaky ----
    #pragma unroll
    for (int u = 0; u < 8; u++)
        #pragma unroll
        for (int vp = 0; vp < 4; vp++) acc[u][vp] = bias0[u];
    mm8x8p<131>(Abuf, Wsm, tx, ty, acc);
    #pragma unroll
    for (int u = 0; u < 8; u++)
        store_leaky8(Bbuf + (ty * 8 + u) * AW + tx * 8, acc, u);
    __syncthreads();

    // stage W1
    for (int e = tid; e < 128 * 128; e += 256) {
        int i = e & 127, c = e >> 7;
        Wsm[i * AW + c] = w1g[e];
    }
    __syncthreads();

    // ---- layer 2: 128 -> 128, leaky ----
    #pragma unroll
    for (int u = 0; u < 8; u++)
        #pragma unroll
        for (int vp = 0; vp < 4; vp++) acc[u][vp] = bias1[u];
    mm8x8p<128>(Bbuf, Wsm, tx, ty, acc);
    #pragma unroll
    for (int u = 0; u < 8; u++)
        store_leaky8(Abuf + (ty * 8 + u) * AW + tx * 8, acc, u);
    __syncthreads();

    // stage W2
    for (int e = tid; e < 128 * 128; e += 256) {
        int i = e & 127, c = e >> 7;
        Wsm[i * AW + c] = w2g[e];
    }
    __syncthreads();

    // ---- S matrix: s[col][c] = relu(b2[c] + sum_j w2[c][j]*h2[col][j]) -> Bbuf ----
    {
        int col = tid >> 1, chalf = tid & 1;
        float hj[8];
        #pragma unroll
        for (int j = 0; j < 8; j++) hj[j] = h2s[col * 8 + j];
        #pragma unroll 4
        for (int cc = 0; cc < 64; cc++) {
            int c = chalf * 64 + cc;
            float s = sb2[c];
            #pragma unroll
            for (int j = 0; j < 8; j++) s += sw2[c * 8 + j] * hj[j];
            Bbuf[col * AW + c] = fmaxf(s, 0.f);
        }
    }

    // ---- layer 3: 128 -> 128 ----
    #pragma unroll
    for (int u = 0; u < 8; u++)
        #pragma unroll
        for (int vp = 0; vp < 4; vp++) acc[u][vp] = bias2[u];
    mm8x8p<128>(Abuf, Wsm, tx, ty, acc);
    __syncthreads();   // S writes visible

    // ---- epilogue: partial[u] = sum_v S[col_v][c_u] * leaky(acc[u][v]) ----
    {
        float partial[8];
        #pragma unroll
        for (int u = 0; u < 8; u++) partial[u] = 0.f;
        #pragma unroll
        for (int vp = 0; vp < 4; vp++) {
            float e0[8], e1[8];
            #pragma unroll
            for (int u = 0; u < 8; u++) unp2(acc[u][vp], e0[u], e1[u]);
            {
                int col = tx * 8 + 2 * vp;
                float4 s0 = *(const float4*)(Bbuf + col * AW + ty * 8);
                float4 s1 = *(const float4*)(Bbuf + col * AW + ty * 8 + 4);
                float s[8] = {s0.x, s0.y, s0.z, s0.w, s1.x, s1.y, s1.z, s1.w};
                #pragma unroll
                for (int u = 0; u < 8; u++) partial[u] += s[u] * leakyf(e0[u]);
            }
            {
                int col = tx * 8 + 2 * vp + 1;
                float4 s0 = *(const float4*)(Bbuf + col * AW + ty * 8);
                float4 s1 = *(const float4*)(Bbuf + col * AW + ty * 8 + 4);
                float s[8] = {s0.x, s0.y, s0.z, s0.w, s1.x, s1.y, s1.z, s1.w};
                #pragma unroll
                for (int u = 0; u < 8; u++) partial[u] += s[u] * leakyf(e1[u]);
            }
        }
        #pragma unroll
        for (int u = 0; u < 8; u++) ps[tx * 128 + ty * 8 + u] = partial[u];
    }
    __syncthreads();
    for (int e = tid; e < 1024; e += 256) {
        int tn = e >> 7, c = e & 127;
        g_p2p[(size_t)(base + tn) * CO + c] = ps[(2 * tn) * 128 + c] + ps[(2 * tn + 1) * 128 + c];
    }
}

// ---------------- patch aggregation ----------------
__global__ void __launch_bounds__(128) k_patch(
    const float* __restrict__ n2w0, const float* __restrict__ n2b0,
    const float* __restrict__ n2w1, const float* __restrict__ n2b1,
    const float* __restrict__ n2w2, const float* __restrict__ n2b2,
    float* __restrict__ out)
{
    __shared__ float h2s[16][8];
    __shared__ int js[16];
    int q = blockIdx.x;
    int b = q / N1, n = q % N1;
    int tid = threadIdx.x;
    if (tid < 16) {
        int j = g_idx2[q * KN + tid];
        js[tid] = j;
        float dx0 = g_x1T[(b * N1 + j) * 3 + 0] - g_x1T[q * 3 + 0];
        float dx1 = g_x1T[(b * N1 + j) * 3 + 1] - g_x1T[q * 3 + 1];
        float dx2 = g_x1T[(b * N1 + j) * 3 + 2] - g_x1T[q * 3 + 2];
        float h[8];
        #pragma unroll
        for (int jj = 0; jj < 8; jj++) {
            float s = n2w0[jj * 3 + 0] * dx0 + n2w0[jj * 3 + 1] * dx1 + n2w0[jj * 3 + 2] * dx2 + n2b0[jj];
            h[jj] = fmaxf(s, 0.f);
        }
        #pragma unroll
        for (int jj = 0; jj < 8; jj++) {
            float s = n2b1[jj];
            #pragma unroll
            for (int m = 0; m < 8; m++) s += n2w1[jj * 8 + m] * h[m];
            h2s[tid][jj] = fmaxf(s, 0.f);
        }
    }
    __syncthreads();
    int c = tid;
    float w2r[8];
    #pragma unroll
    for (int j = 0; j < 8; j++) w2r[j] = n2w2[c * 8 + j];
    float bc = n2b2[c];
    float acc = 0.f;
    #pragma unroll
    for (int k = 0; k < KN; k++) {
        float s = bc;
        #pragma unroll
        for (int j = 0; j < 8; j++) s += w2r[j] * h2s[k][j];
        s = fmaxf(s, 0.f);
        acc += s * g_p2p[((size_t)b * N1 + js[k]) * CO + c];
    }
    out[(size_t)b * CO * N1 + (size_t)c * N1 + n] = acc;
}

// ---------------- launch ----------------
extern "C" void kernel_launch(void* const* d_in, const int* in_sizes, int n_in,
                              void* d_out, int out_size)
{
    int s = (n_in >= 31) ? 0 : -2;
    const float* xyz1 = (const float*)d_in[0];
    const float* xyz2 = (const float*)d_in[1];
    const float* pts1 = (const float*)d_in[2];
    const float* pts2 = (const float*)d_in[3];
    const float* vel1 = (const float*)d_in[4];
    const float* fcc  = (const float*)d_in[8 + s];
    const float* fcv  = (const float*)d_in[9 + s];
    const float* wxyz = (const float*)d_in[10 + s];
    const float* wpts = (const float*)d_in[12 + s];
    const float* mw0 = (const float*)d_in[13 + s];
    const float* mb0 = (const float*)d_in[14 + s];
    const float* mw1 = (const float*)d_in[15 + s];
    const float* mb1 = (const float*)d_in[16 + s];
    const float* mw2 = (const float*)d_in[17 + s];
    const float* mb2 = (const float*)d_in[18 + s];
    const float* n1w0 = (const float*)d_in[19 + s];
    const float* n1b0 = (const float*)d_in[20 + s];
    const float* n2w0 = (const float*)d_in[21 + s];
    const float* n2b0 = (const float*)d_in[22 + s];
    const float* n1w1 = (const float*)d_in[23 + s];
    const float* n1b1 = (const float*)d_in[24 + s];
    const float* n2w1 = (const float*)d_in[25 + s];
    const float* n2b1 = (const float*)d_in[26 + s];
    const float* n1w2 = (const float*)d_in[27 + s];
    const float* n1b2 = (const float*)d_in[28 + s];
    const float* n2w2 = (const float*)d_in[29 + s];
    const float* n2b2 = (const float*)d_in[30 + s];

    float* out = (float*)d_out;
    const int patch_elems = BATCH * CO * N1;
    const int vw_elems = BATCH * N1 * 3;
    float* out_vw = (out_size >= patch_elems + vw_elems) ? (out + patch_elems) : nullptr;

    cudaFuncSetAttribute(k_mlp, cudaFuncAttributeMaxDynamicSharedMemorySize, (int)MLP_SMEM);

    const int prep_total = 2 * BATCH * CP * N1 + 2 * BATCH * DD * N1 + 2 * BATCH * 3 * N1;

    k_rigid<<<(BATCH * N1 + 127) / 128, 128>>>(xyz1, vel1, fcc, fcv, out_vw);
    k_prep<<<(prep_total + 255) / 256, 256>>>(xyz1, xyz2, pts1, pts2, wxyz, wpts);
    k_norms<<<(BATCH * 4096 + 127) / 128, 128>>>();
    k_comb<<<(BATCH * CP * N1 + 255) / 256, 256>>>();

    dim3 gg(N2 / 128, N1 / 128, BATCH);
    k_dist<<<gg, 256>>>(0);
    k_topk<<<BATCH * N1, 128>>>(0);

    k_mlp<<<(BATCH * N1) / TNP, 256, MLP_SMEM>>>(mw0, mb0, mw1, mb1, mw2, mb2,
                                                 n1w0, n1b0, n1w1, n1b1, n1w2, n1b2);

    k_dist<<<gg, 256>>>(1);
    k_topk<<<BATCH * N1, 128>>>(1);

    k_patch<<<BATCH * N1, 128>>>(n2w0, n2b0, n2w1, n2b1, n2w2, n2b2, out);
}

// round 5
// speedup vs baseline: 1.3426x; 1.0015x over previous
#include <cuda_runtime.h>
#include <math.h>

#define BATCH 2
#define N1 4096
#define N2 4096
#define DD 64
#define KN 16
#define KCC 8
#define CP 80      // padded feature channels (67 / 70 used)
#define CO 128

// ---------------- scratch (static device memory; no runtime alloc) ----------------
__device__ float g_dist[(size_t)BATCH * N1 * N2];        // 134 MB
__device__ float g_F1[BATCH * CP * N1];
__device__ float g_F2[BATCH * CP * N2];
__device__ float g_CB[BATCH * CP * N1];
__device__ float g_nA[BATCH * N1];
__device__ float g_nB[BATCH * N2];
__device__ float g_nC[BATCH * N1];
__device__ int   g_idx1[BATCH * N1 * KN];
__device__ int   g_idx2[BATCH * N1 * KN];
__device__ float g_vw[BATCH * N1 * 3];
__device__ float g_wf[BATCH * N1];
__device__ float g_wr[BATCH * N1];
__device__ float g_p1T[BATCH * N1 * DD];
__device__ float g_p2T[BATCH * N2 * DD];
__device__ float g_x1T[BATCH * N1 * 3];
__device__ float g_x2T[BATCH * N2 * 3];
__device__ float g_p2p[(size_t)BATCH * N1 * CO];

__device__ __forceinline__ float leakyf(float x) { return x >= 0.f ? x : 0.1f * x; }
__device__ __forceinline__ unsigned long long u64min(unsigned long long a, unsigned long long b) {
    return a < b ? a : b;
}

// ---- packed f32x2 helpers ----
__device__ __forceinline__ unsigned long long bcast2(float x) {
    unsigned long long r;
    asm("mov.b64 %0, {%1,%1};" : "=l"(r) : "f"(x));
    return r;
}
__device__ __forceinline__ unsigned long long fma2(unsigned long long a, unsigned long long b,
                                                   unsigned long long c) {
    unsigned long long d;
    asm("fma.rn.f32x2 %0, %1, %2, %3;" : "=l"(d) : "l"(a), "l"(b), "l"(c));
    return d;
}
__device__ __forceinline__ void unp2(unsigned long long v, float& lo, float& hi) {
    asm("mov.b64 {%0,%1}, %2;" : "=f"(lo), "=f"(hi) : "l"(v));
}

// ---------------- rigid 3x3 least squares + mask ----------------
__global__ void k_rigid(const float* __restrict__ xyz1, const float* __restrict__ vel1,
                        const float* __restrict__ fcc, const float* __restrict__ fcv,
                        float* __restrict__ out_vw)
{
    int t = blockIdx.x * blockDim.x + threadIdx.x;
    if (t >= BATCH * N1) return;
    int b = t / N1, n = t % N1;
    const float* cc = fcc + (size_t)t * KCC * 3;
    const float* cv = fcv + (size_t)t * KCC;
    double A00 = 1e-6, A01 = 0, A02 = 0, A11 = 1e-6, A12 = 0, A22 = 1e-6;
    double r0 = 0, r1 = 0, r2 = 0;
    for (int k = 0; k < KCC; k++) {
        double x = cc[k * 3 + 0], y = cc[k * 3 + 1], z = cc[k * 3 + 2];
        double inv = 1.0 / sqrt(x * x + y * y + z * z);
        x *= inv; y *= inv; z *= inv;
        A00 += x * x; A01 += x * y; A02 += x * z;
        A11 += y * y; A12 += y * z; A22 += z * z;
        double v = (double)cv[k];
        r0 += x * v; r1 += y * v; r2 += z * v;
    }
    double c00 = A11 * A22 - A12 * A12;
    double c01 = A01 * A22 - A12 * A02;
    double c02 = A01 * A12 - A11 * A02;
    double det = A00 * c00 - A01 * c01 + A02 * c02;
    double id = 1.0 / det;
    double v0 = (r0 * c00 - A01 * (r1 * A22 - A12 * r2) + A02 * (r1 * A12 - A11 * r2)) * id;
    double v1 = (A00 * (r1 * A22 - A12 * r2) - r0 * c01 + A02 * (A01 * r2 - r1 * A02)) * id;
    double v2 = (A00 * (A11 * r2 - r1 * A12) - A01 * (A01 * r2 - r1 * A02) + r0 * c02) * id;

    float fx = xyz1[(b * 3 + 0) * N1 + n];
    float fy = xyz1[(b * 3 + 1) * N1 + n];
    float fz = xyz1[(b * 3 + 2) * N1 + n];
    double inl = 1.0 / sqrt((double)fx * fx + (double)fy * fy + (double)fz * fz);
    double err = fabs((v0 * fx + v1 * fy + v2 * fz) * inl - (double)vel1[t]);
    bool m = (err <= 5.0);
    g_wf[t] = m ? 0.1f : 0.9f;
    g_wr[t] = m ? 0.9f : 0.1f;
    g_vw[t * 3 + 0] = (float)v0;
    g_vw[t * 3 + 1] = (float)v1;
    g_vw[t * 3 + 2] = (float)v2;
    if (out_vw) {
        out_vw[t * 3 + 0] = (float)v0;
        out_vw[t * 3 + 1] = (float)v1;
        out_vw[t * 3 + 2] = (float)v2;
    }
}

// ---------------- fused: weighted feature build + xyz transposes ----------------
__global__ void k_prep(const float* __restrict__ xyz1, const float* __restrict__ xyz2,
                       const float* __restrict__ pts1, const float* __restrict__ pts2,
                       const float* __restrict__ wxyz_p, const float* __restrict__ wpts_p)
{
    float wx = *wxyz_p, wp = *wpts_p;
    const int totalF = BATCH * CP * N1;          // per F matrix
    const int tx3 = BATCH * 3 * N1;              // per xyz transpose
    const int total = 2 * totalF + 2 * tx3;
    for (int e = blockIdx.x * blockDim.x + threadIdx.x; e < total;
         e += gridDim.x * blockDim.x) {
        if (e < 2 * totalF) {
            int which = e / totalF;
            int r = e % totalF;
            int b = r / (CP * N1);
            int c = (r / N1) % CP;
            int n = r % N1;
            const float* xyz = which ? xyz2 : xyz1;
            const float* pts = which ? pts2 : pts1;
            float* F = which ? g_F2 : g_F1;
            float v = 0.f;
            if (c < 3) v = wx * xyz[(b * 3 + c) * N1 + n];
            else if (c < 67) v = wp * pts[(b * DD + (c - 3)) * N1 + n];
            F[r] = v;
        } else {
            int r = e - 2 * totalF;
            if (r < tx3) {
                int b = r / (3 * N1), c = (r / N1) % 3, n = r % N1;
                g_x1T[(b * N1 + n) * 3 + c] = xyz1[r];
            } else {
                r -= tx3;
                int b = r / (3 * N1), c = (r / N1) % 3, n = r % N1;
                g_x2T[(b * N2 + n) * 3 + c] = xyz2[r];
            }
        }
    }
}

// ---------------- coalesced tiled transpose: [B][C][N] -> [B][N][C], C=64 ----------------
__global__ void __launch_bounds__(256) k_transp(const float* __restrict__ src1,
                                                const float* __restrict__ src2)
{
    __shared__ float t[32][33];
    // grid: (N/32, C/32 * B * 2)
    int zc = blockIdx.y;          // 0..(2*BATCH*2-1): [which][b][ctile]
    int ct = zc & 1;
    int b = (zc >> 1) & (BATCH - 1);
    int which = zc >> 2;
    const float* src = which ? src2 : src1;
    float* dst = which ? g_p2T : g_p1T;
    int n0 = blockIdx.x * 32;
    int c0 = ct * 32;
    int lx = threadIdx.x & 31, ly = threadIdx.x >> 5;   // 32 x 8
    #pragma unroll
    for (int r = 0; r < 4; r++) {
        int c = c0 + ly + r * 8;
        t[ly + r * 8][lx] = src[((size_t)b * DD + c) * N1 + n0 + lx];
    }
    __syncthreads();
    #pragma unroll
    for (int r = 0; r < 4; r++) {
        int n = n0 + ly + r * 8;
        dst[((size_t)b * N1 + n) * DD + c0 + lx] = t[lx][ly + r * 8];
    }
}

// ---------------- all three squared norms in one launch ----------------
__global__ void k_norms()
{
    int t = blockIdx.x * blockDim.x + threadIdx.x;
    if (t >= BATCH * 4096) return;
    int b = t / 4096, n = t % 4096;
    float sA = 0.f, sB = 0.f;
    #pragma unroll 8
    for (int c = 0; c < CP; c++) {
        float a = g_F1[(b * CP + c) * 4096 + n];
        float bb = g_F2[(b * CP + c) * 4096 + n];
        sA += a * a;
        sB += bb * bb;
    }
    g_nA[t] = sA;
    g_nB[t] = sB;
    float wf = g_wf[t], wr = g_wr[t];
    float v0 = g_vw[t * 3 + 0], v1 = g_vw[t * 3 + 1], v2 = g_vw[t * 3 + 2];
    g_nC[t] = wf * wf * sA + wr * wr * (v0 * v0 + v1 * v1 + v2 * v2);
}

// ---------------- comb features for second KNN ----------------
__global__ void k_comb()
{
    const int total = BATCH * CP * N1;
    for (int e = blockIdx.x * blockDim.x + threadIdx.x; e < total;
         e += gridDim.x * blockDim.x) {
        int b = e / (CP * N1);
        int c = (e / N1) % CP;
        int n = e % N1;
        float v = 0.f;
        if (c < 67) v = g_wf[b * N1 + n] * g_F1[e];
        else if (c < 70) v = g_wr[b * N1 + n] * g_vw[(b * N1 + n) * 3 + (c - 67)];
        g_CB[e] = v;
    }
}

// ---------------- distance matrix GEMM (FFMA2 packed) ----------------
__global__ void __launch_bounds__(256) k_dist(int sel)
{
    __shared__ float As[16][132];
    __shared__ float Bs[16][132];
    const float* FA = sel ? g_CB : g_F1;
    const float* FB = sel ? g_CB : g_F2;
    const float* nAv = sel ? g_nC : g_nA;
    const float* nBv = sel ? g_nC : g_nB;

    int b = blockIdx.z;
    int i0 = blockIdx.y * 128, j0 = blockIdx.x * 128;
    const float* Ab = FA + (size_t)b * CP * N1;
    const float* Bb = FB + (size_t)b * CP * N2;
    int tid = threadIdx.x;
    int tx = tid & 15, ty = tid >> 4;

    unsigned long long acc2[8][4];
    #pragma unroll
    for (int r = 0; r < 8; r++)
        #pragma unroll
        for (int sp = 0; sp < 4; sp++) acc2[r][sp] = 0ull;

    for (int kc = 0; kc < CP; kc += 16) {
        #pragma unroll
        for (int l = 0; l < 8; l++) {
            int e = tid + l * 256;
            int r = e >> 7, c = e & 127;
            As[r][c] = Ab[(kc + r) * N1 + i0 + c];
            Bs[r][c] = Bb[(kc + r) * N2 + j0 + c];
        }
        __syncthreads();
        #pragma unroll
        for (int kk = 0; kk < 16; kk++) {
            float4 a0 = *(const float4*)&As[kk][ty * 4];
            float4 a1 = *(const float4*)&As[kk][64 + ty * 4];
            ulonglong2 b0 = *(const ulonglong2*)&Bs[kk][tx * 4];
            ulonglong2 b1 = *(const ulonglong2*)&Bs[kk][64 + tx * 4];
            unsigned long long br[4] = {b0.x, b0.y, b1.x, b1.y};
            unsigned long long aa[8];
            aa[0] = bcast2(a0.x); aa[1] = bcast2(a0.y); aa[2] = bcast2(a0.z); aa[3] = bcast2(a0.w);
            aa[4] = bcast2(a1.x); aa[5] = bcast2(a1.y); aa[6] = bcast2(a1.z); aa[7] = bcast2(a1.w);
            #pragma unroll
            for (int r = 0; r < 8; r++)
                #pragma unroll
                for (int sp = 0; sp < 4; sp++)
                    acc2[r][sp] = fma2(aa[r], br[sp], acc2[r][sp]);
        }
        __syncthreads();
    }
    float* drow = g_dist + (size_t)b * N1 * N2;
    #pragma unroll
    for (int r = 0; r < 8; r++) {
        int i = i0 + ((r < 4) ? (ty * 4 + r) : (64 + ty * 4 + (r - 4)));
        float ni = nAv[b * N1 + i];
        #pragma unroll
        for (int sp = 0; sp < 4; sp++) {
            float d0, d1;
            unp2(acc2[r][sp], d0, d1);
            int jj = j0 + ((sp < 2) ? (tx * 4 + sp * 2) : (64 + tx * 4 + (sp - 2) * 2));
            float e0 = ni - 2.f * d0 + nBv[b * N2 + jj];
            float e1 = ni - 2.f * d1 + nBv[b * N2 + jj + 1];
            drow[(size_t)i * N2 + jj] = fmaxf(e0, 0.f);
            drow[(size_t)i * N2 + jj + 1] = fmaxf(e1, 0.f);
        }
    }
}

// ---------------- top-K via incremental segment-min selection ----------------
__global__ void __launch_bounds__(128) k_topk(int sel)
{
    __shared__ unsigned long long keys[N2];     // 32 KB
    __shared__ unsigned long long segmin[256];
    __shared__ unsigned long long red[4];
    __shared__ int s_ext;
    int q = blockIdx.x;
    const float* row = g_dist + (size_t)q * N2;
    int* idxo = sel ? g_idx2 : g_idx1;
    int tid = threadIdx.x;

    #pragma unroll
    for (int s2 = 0; s2 < 2; s2++) {
        int seg = tid * 2 + s2;
        int basej = seg * 16;
        unsigned long long mn = ~0ull;
        #pragma unroll
        for (int i = 0; i < 4; i++) {
            float4 f = *(const float4*)(row + basej + i * 4);
            unsigned long long k0 = ((unsigned long long)__float_as_uint(f.x) << 32) | (unsigned)(basej + i * 4 + 0);
            unsigned long long k1 = ((unsigned long long)__float_as_uint(f.y) << 32) | (unsigned)(basej + i * 4 + 1);
            unsigned long long k2 = ((unsigned long long)__float_as_uint(f.z) << 32) | (unsigned)(basej + i * 4 + 2);
            unsigned long long k3 = ((unsigned long long)__float_as_uint(f.w) << 32) | (unsigned)(basej + i * 4 + 3);
            keys[basej + i * 4 + 0] = k0;
            keys[basej + i * 4 + 1] = k1;
            keys[basej + i * 4 + 2] = k2;
            keys[basej + i * 4 + 3] = k3;
            mn = u64min(mn, u64min(u64min(k0, k1), u64min(k2, k3)));
        }
        segmin[seg] = mn;
    }
    __syncthreads();

    for (int k = 0; k < KN; k++) {
        unsigned long long m = u64min(segmin[tid], segmin[tid + 128]);
        #pragma unroll
        for (int o = 16; o; o >>= 1) {
            unsigned long long v = __shfl_xor_sync(0xffffffffu, m, o);
            m = u64min(m, v);
        }
        if ((tid & 31) == 0) red[tid >> 5] = m;
        __syncthreads();
        if (tid == 0) {
            m = u64min(u64min(red[0], red[1]), u64min(red[2], red[3]));
            int j = (int)(unsigned)(m & 0xffffffffULL);
            idxo[q * KN + k] = j;
            keys[j] = ~0ull;
            s_ext = j;
        }
        __syncthreads();
        if (k < KN - 1) {
            int seg = s_ext >> 4;
            if (tid < 16) {
                unsigned long long v = keys[seg * 16 + tid];
                #pragma unroll
                for (int o = 8; o; o >>= 1) {
                    unsigned long long w = __shfl_xor_sync(0xffffu, v, o);
                    v = u64min(v, w);
                }
                if (tid == 0) segmin[seg] = v;
            }
            __syncthreads();
        }
    }
}

// ---------------- fused MLP: 8x8 register-tiled block GEMM (FFMA2 packed) ----------------
#define TNP 8
#define AW 132
#define OFF_W    0
#define OFF_A    (131 * AW)
#define OFF_B    (OFF_A + 131 * AW)
#define OFF_H2   (OFF_B + 128 * AW)
#define OFF_SW2  (OFF_H2 + 128 * 8)
#define OFF_SB2  (OFF_SW2 + 128 * 8)
#define OFF_PS   (OFF_SB2 + 128)
#define OFF_IDX  (OFF_PS + 16 * 128)
#define MLP_SMEM ((OFF_IDX + 128) * 4)

template<int KIN>
__device__ __forceinline__ void mm8x8p(const float* __restrict__ A, const float* __restrict__ W,
                                       int tx, int ty, unsigned long long (&acc)[8][4])
{
    #pragma unroll 4
    for (int kk = 0; kk < KIN; kk++) {
        ulonglong2 a01 = *(const ulonglong2*)(A + kk * AW + tx * 8);
        ulonglong2 a23 = *(const ulonglong2*)(A + kk * AW + tx * 8 + 4);
        float4 w0 = *(const float4*)(W + kk * AW + ty * 8);
        float4 w1 = *(const float4*)(W + kk * AW + ty * 8 + 4);
        unsigned long long av[4] = {a01.x, a01.y, a23.x, a23.y};
        unsigned long long wb[8];
        wb[0] = bcast2(w0.x); wb[1] = bcast2(w0.y); wb[2] = bcast2(w0.z); wb[3] = bcast2(w0.w);
        wb[4] = bcast2(w1.x); wb[5] = bcast2(w1.y); wb[6] = bcast2(w1.z); wb[7] = bcast2(w1.w);
        #pragma unroll
        for (int u = 0; u < 8; u++)
            #pragma unroll
            for (int vp = 0; vp < 4; vp++)
                acc[u][vp] = fma2(wb[u], av[vp], acc[u][vp]);
    }
}

__device__ __forceinline__ void store_leaky8(float* dst, const unsigned long long (&acc)[8][4],
                                             int u)
{
    float x[8];
    unp2(acc[u][0], x[0], x[1]);
    unp2(acc[u][1], x[2], x[3]);
    unp2(acc[u][2], x[4], x[5]);
    unp2(acc[u][3], x[6], x[7]);
    float4 o0, o1;
    o0.x = leakyf(x[0]); o0.y = leakyf(x[1]); o0.z = leakyf(x[2]); o0.w = leakyf(x[3]);
    o1.x = leakyf(x[4]); o1.y = leakyf(x[5]); o1.z = leakyf(x[6]); o1.w = leakyf(x[7]);
    *(float4*)dst = o0;
    *(float4*)(dst + 4) = o1;
}

__global__ void __launch_bounds__(256) k_mlp(
    const float* __restrict__ w0g, const float* __restrict__ b0g,
    const float* __restrict__ w1g, const float* __restrict__ b1g,
    const float* __restrict__ w2g, const float* __restrict__ b2g,
    const float* __restrict__ n1w0, const float* __restrict__ n1b0,
    const float* __restrict__ n1w1, const float* __restrict__ n1b1,
    const float* __restrict__ n1w2, const float* __restrict__ n1b2)
{
    extern __shared__ float sm[];
    float* Wsm = sm + OFF_W;
    float* Abuf = sm + OFF_A;
    float* Bbuf = sm + OFF_B;
    float* h2s = sm + OFF_H2;
    float* sw2 = sm + OFF_SW2;
    float* sb2 = sm + OFF_SB2;
    float* ps  = sm + OFF_PS;
    int* idxs = (int*)(sm + OFF_IDX);

    int tid = threadIdx.x;
    int tx = tid & 15, ty = tid >> 4;
    int base = blockIdx.x * TNP;

    if (tid < 128) {
        idxs[tid] = g_idx1[base * KN + tid];
        #pragma unroll
        for (int r = 0; r < 8; r++) sw2[tid + 128 * r] = n1w2[tid + 128 * r];
        sb2[tid] = n1b2[tid];
    }
    __syncthreads();

    // stage A [131][128]
    for (int e = tid; e < 131 * 128; e += 256) {
        int i = e >> 7, col = e & 127;
        int tn = col >> 4;
        int pt = base + tn;
        int b = pt >> 12;
        int j = idxs[col];
        float v;
        if (i < 64) v = g_p1T[(size_t)pt * DD + i];
        else if (i < 128) v = g_p2T[((size_t)b * N2 + j) * DD + (i - 64)];
        else v = g_x2T[(b * N2 + j) * 3 + (i - 128)] - g_x1T[pt * 3 + (i - 128)];
        Abuf[i * AW + col] = v;
    }
    // stage W0 transposed [in 131][out 128]
    for (int e = tid; e < 128 * 131; e += 256) {
        int i = e % 131, c = e / 131;
        Wsm[i * AW + c] = w0g[e];
    }
    __syncthreads();

    // weight-net 1 (3->8->8) per column -> h2s[col][8]
    if (tid < 128) {
        int col = tid;
        float dx0 = Abuf[128 * AW + col];
        float dx1 = Abuf[129 * AW + col];
        float dx2 = Abuf[130 * AW + col];
        float h[8];
        #pragma unroll
        for (int j = 0; j < 8; j++) {
            float s = n1w0[j * 3 + 0] * dx0 + n1w0[j * 3 + 1] * dx1 + n1w0[j * 3 + 2] * dx2 + n1b0[j];
            h[j] = fmaxf(s, 0.f);
        }
        #pragma unroll
        for (int j = 0; j < 8; j++) {
            float s = n1b1[j];
            #pragma unroll
            for (int m = 0; m < 8; m++) s += n1w1[j * 8 + m] * h[m];
            h2s[col * 8 + j] = fmaxf(s, 0.f);
        }
    }
    __syncthreads();

    unsigned long long bias0[8], bias1[8], bias2[8];
    #pragma unroll
    for (int u = 0; u < 8; u++) {
        bias0[u] = bcast2(b0g[ty * 8 + u]);
        bias1[u] = bcast2(b1g[ty * 8 + u]);
        bias2[u] = bcast2(b2g[ty * 8 + u]);
    }

    unsigned long long acc[8][4];

    // ---- layer 1: 131 -> 128, leaky ----
    #pragma unroll
    for (int u = 0; u < 8; u++)
        #pragma unroll
        for (int vp = 0; vp < 4; vp++) acc[u][vp] = bias0[u];
    mm8x8p<131>(Abuf, Wsm, tx, ty, acc);
    #pragma unroll
    for (int u = 0; u < 8; u++)
        store_leaky8(Bbuf + (ty * 8 + u) * AW + tx * 8, acc, u);
    __syncthreads();

    // stage W1
    for (int e = tid; e < 128 * 128; e += 256) {
        int i = e & 127, c = e >> 7;
        Wsm[i * AW + c] = w1g[e];
    }
    __syncthreads();

    // ---- layer 2: 128 -> 128, leaky ----
    #pragma unroll
    for (int u = 0; u < 8; u++)
        #pragma unroll
        for (int vp = 0; vp < 4; vp++) acc[u][vp] = bias1[u];
    mm8x8p<128>(Bbuf, Wsm, tx, ty, acc);
    #pragma unroll
    for (int u = 0; u < 8; u++)
        store_leaky8(Abuf + (ty * 8 + u) * AW + tx * 8, acc, u);
    __syncthreads();

    // stage W2
    for (int e = tid; e < 128 * 128; e += 256) {
        int i = e & 127, c = e >> 7;
        Wsm[i * AW + c] = w2g[e];
    }
    __syncthreads();

    // ---- S matrix -> Bbuf ----
    {
        int col = tid >> 1, chalf = tid & 1;
        float hj[8];
        #pragma unroll
        for (int j = 0; j < 8; j++) hj[j] = h2s[col * 8 + j];
        #pragma unroll 4
        for (int cc = 0; cc < 64; cc++) {
            int c = chalf * 64 + cc;
            float s = sb2[c];
            #pragma unroll
            for (int j = 0; j < 8; j++) s += sw2[c * 8 + j] * hj[j];
            Bbuf[col * AW + c] = fmaxf(s, 0.f);
        }
    }

    // ---- layer 3: 128 -> 128 ----
    #pragma unroll
    for (int u = 0; u < 8; u++)
        #pragma unroll
        for (int vp = 0; vp < 4; vp++) acc[u][vp] = bias2[u];
    mm8x8p<128>(Abuf, Wsm, tx, ty, acc);
    __syncthreads();   // S writes visible

    // ---- epilogue ----
    {
        float partial[8];
        #pragma unroll
        for (int u = 0; u < 8; u++) partial[u] = 0.f;
        #pragma unroll
        for (int vp = 0; vp < 4; vp++) {
            float e0[8], e1[8];
            #pragma unroll
            for (int u = 0; u < 8; u++) unp2(acc[u][vp], e0[u], e1[u]);
            {
                int col = tx * 8 + 2 * vp;
                float4 s0 = *(const float4*)(Bbuf + col * AW + ty * 8);
                float4 s1 = *(const float4*)(Bbuf + col * AW + ty * 8 + 4);
                float s[8] = {s0.x, s0.y, s0.z, s0.w, s1.x, s1.y, s1.z, s1.w};
                #pragma unroll
                for (int u = 0; u < 8; u++) partial[u] += s[u] * leakyf(e0[u]);
            }
            {
                int col = tx * 8 + 2 * vp + 1;
                float4 s0 = *(const float4*)(Bbuf + col * AW + ty * 8);
                float4 s1 = *(const float4*)(Bbuf + col * AW + ty * 8 + 4);
                float s[8] = {s0.x, s0.y, s0.z, s0.w, s1.x, s1.y, s1.z, s1.w};
                #pragma unroll
                for (int u = 0; u < 8; u++) partial[u] += s[u] * leakyf(e1[u]);
            }
        }
        #pragma unroll
        for (int u = 0; u < 8; u++) ps[tx * 128 + ty * 8 + u] = partial[u];
    }
    __syncthreads();
    for (int e = tid; e < 1024; e += 256) {
        int tn = e >> 7, c = e & 127;
        g_p2p[(size_t)(base + tn) * CO + c] = ps[(2 * tn) * 128 + c] + ps[(2 * tn + 1) * 128 + c];
    }
}

// ---------------- patch aggregation ----------------
__global__ void __launch_bounds__(128) k_patch(
    const float* __restrict__ n2w0, const float* __restrict__ n2b0,
    const float* __restrict__ n2w1, const float* __restrict__ n2b1,
    const float* __restrict__ n2w2, const float* __restrict__ n2b2,
    float* __restrict__ out)
{
    __shared__ float h2s[16][8];
    __shared__ int js[16];
    int q = blockIdx.x;
    int b = q / N1, n = q % N1;
    int tid = threadIdx.x;
    if (tid < 16) {
        int j = g_idx2[q * KN + tid];
        js[tid] = j;
        float dx0 = g_x1T[(b * N1 + j) * 3 + 0] - g_x1T[q * 3 + 0];
        float dx1 = g_x1T[(b * N1 + j) * 3 + 1] - g_x1T[q * 3 + 1];
        float dx2 = g_x1T[(b * N1 + j) * 3 + 2] - g_x1T[q * 3 + 2];
        float h[8];
        #pragma unroll
        for (int jj = 0; jj < 8; jj++) {
            float s = n2w0[jj * 3 + 0] * dx0 + n2w0[jj * 3 + 1] * dx1 + n2w0[jj * 3 + 2] * dx2 + n2b0[jj];
            h[jj] = fmaxf(s, 0.f);
        }
        #pragma unroll
        for (int jj = 0; jj < 8; jj++) {
            float s = n2b1[jj];
            #pragma unroll
            for (int m = 0; m < 8; m++) s += n2w1[jj * 8 + m] * h[m];
            h2s[tid][jj] = fmaxf(s, 0.f);
        }
    }
    __syncthreads();
    int c = tid;
    float w2r[8];
    #pragma unroll
    for (int j = 0; j < 8; j++) w2r[j] = n2w2[c * 8 + j];
    float bc = n2b2[c];
    float acc = 0.f;
    #pragma unroll
    for (int k = 0; k < KN; k++) {
        float s = bc;
        #pragma unroll
        for (int j = 0; j < 8; j++) s += w2r[j] * h2s[k][j];
        s = fmaxf(s, 0.f);
        acc += s * g_p2p[((size_t)b * N1 + js[k]) * CO + c];
    }
    out[(size_t)b * CO * N1 + (size_t)c * N1 + n] = acc;
}

// ---------------- launch ----------------
extern "C" void kernel_launch(void* const* d_in, const int* in_sizes, int n_in,
                              void* d_out, int out_size)
{
    int s = (n_in >= 31) ? 0 : -2;
    const float* xyz1 = (const float*)d_in[0];
    const float* xyz2 = (const float*)d_in[1];
    const float* pts1 = (const float*)d_in[2];
    const float* pts2 = (const float*)d_in[3];
    const float* vel1 = (const float*)d_in[4];
    const float* fcc  = (const float*)d_in[8 + s];
    const float* fcv  = (const float*)d_in[9 + s];
    const float* wxyz = (const float*)d_in[10 + s];
    const float* wpts = (const float*)d_in[12 + s];
    const float* mw0 = (const float*)d_in[13 + s];
    const float* mb0 = (const float*)d_in[14 + s];
    const float* mw1 = (const float*)d_in[15 + s];
    const float* mb1 = (const float*)d_in[16 + s];
    const float* mw2 = (const float*)d_in[17 + s];
    const float* mb2 = (const float*)d_in[18 + s];
    const float* n1w0 = (const float*)d_in[19 + s];
    const float* n1b0 = (const float*)d_in[20 + s];
    const float* n2w0 = (const float*)d_in[21 + s];
    const float* n2b0 = (const float*)d_in[22 + s];
    const float* n1w1 = (const float*)d_in[23 + s];
    const float* n1b1 = (const float*)d_in[24 + s];
    const float* n2w1 = (const float*)d_in[25 + s];
    const float* n2b1 = (const float*)d_in[26 + s];
    const float* n1w2 = (const float*)d_in[27 + s];
    const float* n1b2 = (const float*)d_in[28 + s];
    const float* n2w2 = (const float*)d_in[29 + s];
    const float* n2b2 = (const float*)d_in[30 + s];

    float* out = (float*)d_out;
    const int patch_elems = BATCH * CO * N1;
    const int vw_elems = BATCH * N1 * 3;
    float* out_vw = (out_size >= patch_elems + vw_elems) ? (out + patch_elems) : nullptr;

    cudaFuncSetAttribute(k_mlp, cudaFuncAttributeMaxDynamicSharedMemorySize, (int)MLP_SMEM);

    const int prep_total = 2 * BATCH * CP * N1 + 2 * BATCH * 3 * N1;
    dim3 gg(N2 / 128, N1 / 128, BATCH);
    dim3 gt(N1 / 32, 2 * BATCH * 2);

    // order chosen so the ncu capture (skip-5) lands on a heavy kernel:
    // 1 rigid, 2 prep, 3 transp, 4 norms, 5 dist0, 6 topk0, 7 mlp, ...
    k_rigid<<<(BATCH * N1 + 127) / 128, 128>>>(xyz1, vel1, fcc, fcv, out_vw);
    k_prep<<<(prep_total + 255) / 256, 256>>>(xyz1, xyz2, pts1, pts2, wxyz, wpts);
    k_transp<<<gt, 256>>>(pts1, pts2);
    k_norms<<<(BATCH * 4096 + 127) / 128, 128>>>();

    k_dist<<<gg, 256>>>(0);
    k_topk<<<BATCH * N1, 128>>>(0);
    k_mlp<<<(BATCH * N1) / TNP, 256, MLP_SMEM>>>(mw0, mb0, mw1, mb1, mw2, mb2,
                                                 n1w0, n1b0, n1w1, n1b1, n1w2, n1b2);

    k_comb<<<(BATCH * CP * N1 + 255) / 256, 256>>>();
    k_dist<<<gg, 256>>>(1);
    k_topk<<<BATCH * N1, 128>>>(1);

    k_patch<<<BATCH * N1, 128>>>(n2w0, n2b0, n2w1, n2b1, n2w2, n2b2, out);
}